// round 1
// baseline (speedup 1.0000x reference)
#include <cuda_runtime.h>
#include <cstdint>
#include <cstddef>

#define CB 4
#define CE 512
#define CP 1536
#define CH 32
#define CHK 8
#define CD 128
#define TQ 64
#define TK 64
#define NTHREADS 256
#define QPAD 132
#define KPAD 132
#define VPAD 128
#define PPAD 68
#define SCALE_F 0.08838834764831845f

struct __align__(16) Smem {
    float q[TQ][QPAD];
    float k[TK][KPAD];
    float v[TK][VPAD];
    float pt[TK][PPAD];   // transposed probabilities: pt[j][i]
    float m[TQ];
    float l[TQ];
    float scale[TQ];
};

// ---- packed f32x2 helpers (Blackwell sm_103a) ----
__device__ __forceinline__ void ffma2(unsigned long long& d,
                                      unsigned long long a,
                                      unsigned long long b) {
    asm("fma.rn.f32x2 %0, %1, %2, %0;" : "+l"(d) : "l"(a), "l"(b));
}
__device__ __forceinline__ unsigned long long mul2(unsigned long long a,
                                                   unsigned long long b) {
    unsigned long long d;
    asm("mul.rn.f32x2 %0, %1, %2;" : "=l"(d) : "l"(a), "l"(b));
    return d;
}
__device__ __forceinline__ unsigned long long pack2(float lo, float hi) {
    unsigned long long d;
    asm("mov.b64 %0, {%1, %2};" : "=l"(d) : "f"(lo), "f"(hi));
    return d;
}
__device__ __forceinline__ float2 unpack2(unsigned long long p) {
    float2 f;
    asm("mov.b64 {%0, %1}, %2;" : "=f"(f.x), "=f"(f.y) : "l"(p));
    return f;
}

__global__ __launch_bounds__(NTHREADS, 1)
void radix_extend_kernel(const float* __restrict__ q,
                         const float* __restrict__ k,
                         const float* __restrict__ v,
                         const float* __restrict__ kc,
                         const float* __restrict__ vc,
                         float* __restrict__ out) {
    extern __shared__ Smem smem_buf[];
    Smem& s = smem_buf[0];

    const int t  = threadIdx.x;
    const int e0 = blockIdx.x * TQ;
    const int h  = blockIdx.y;
    const int b  = blockIdx.z;
    const int kh = h >> 2;   // GQA group size 4

    // ---- load Q tile, row-major flat copy (coalesced) ----
    {
        const float* qbase = q + ((size_t)(b * CE + e0) * CH + h) * CD;
        #pragma unroll
        for (int u = 0; u < 8; ++u) {
            int f  = t + u * NTHREADS;     // 0..2047
            int i  = f >> 5;               // row within tile
            int d4 = (f & 31) * 4;
            float4 val = *reinterpret_cast<const float4*>(qbase + (size_t)i * (CH * CD) + d4);
            *reinterpret_cast<float4*>(&s.q[i][d4]) = val;
        }
    }
    if (t < TQ) { s.m[t] = -1e30f; s.l[t] = 0.0f; }

    const int tx = t & 15;       // column-group lane (phase 1) / d-group (phase 2)
    const int ty = t >> 4;
    const int i0 = ty * 4;       // 4 query rows owned by this thread (both phases)

    // output accumulators: 4 rows x 4 d-pairs, d = 2*tx + 32*sg (+1)
    unsigned long long oacc[4][4];
    #pragma unroll
    for (int r = 0; r < 4; ++r)
        #pragma unroll
        for (int c = 0; c < 4; ++c) oacc[r][c] = 0ull;

    const int ntiles = (CP + e0 + TQ) / TK;

    for (int kt = 0; kt < ntiles; ++kt) {
        const int s0 = kt * TK;
        __syncthreads();   // previous phase-2 done with s.v / s.pt, phase-1 done with s.k

        // ---- load K/V tile (coalesced, conflict-free STS.128) ----
        #pragma unroll
        for (int u = 0; u < 8; ++u) {
            int f  = t + u * NTHREADS;
            int j  = f >> 5;
            int d4 = (f & 31) * 4;
            int sj = s0 + j;
            const float* krow;
            const float* vrow;
            if (sj < CP) {
                size_t off = ((size_t)(b * CP + sj) * CHK + kh) * CD;
                krow = kc + off; vrow = vc + off;
            } else {
                size_t off = ((size_t)(b * CE + (sj - CP)) * CHK + kh) * CD;
                krow = k + off;  vrow = v + off;
            }
            *reinterpret_cast<float4*>(&s.k[j][d4]) = *reinterpret_cast<const float4*>(krow + d4);
            *reinterpret_cast<float4*>(&s.v[j][d4]) = *reinterpret_cast<const float4*>(vrow + d4);
        }
        __syncthreads();

        // ---- phase 1: S = Q K^T, f32x2 paired over d ----
        // thread owns rows i0..i0+3, cols j = tx + 16*c (c = 0..3)
        unsigned long long acc[4][4];
        #pragma unroll
        for (int r = 0; r < 4; ++r)
            #pragma unroll
            for (int c = 0; c < 4; ++c) acc[r][c] = 0ull;

        #pragma unroll 2
        for (int d4 = 0; d4 < CD; d4 += 4) {
            unsigned long long qv[4][2], kv[4][2];
            #pragma unroll
            for (int r = 0; r < 4; ++r) {
                const ulonglong2 tmp = *reinterpret_cast<const ulonglong2*>(&s.q[i0 + r][d4]);
                qv[r][0] = tmp.x; qv[r][1] = tmp.y;
            }
            #pragma unroll
            for (int c = 0; c < 4; ++c) {
                const ulonglong2 tmp = *reinterpret_cast<const ulonglong2*>(&s.k[tx + 16 * c][d4]);
                kv[c][0] = tmp.x; kv[c][1] = tmp.y;
            }
            #pragma unroll
            for (int r = 0; r < 4; ++r)
                #pragma unroll
                for (int c = 0; c < 4; ++c) {
                    ffma2(acc[r][c], qv[r][0], kv[c][0]);
                    ffma2(acc[r][c], qv[r][1], kv[c][1]);
                }
        }

        // ---- finalize scores, mask, online softmax ----
        float sc[4][4];
        float mt[4];
        #pragma unroll
        for (int r = 0; r < 4; ++r) {
            mt[r] = -1e30f;
            const int lim = CP + e0 + i0 + r;    // key s visible iff s <= lim
            #pragma unroll
            for (int c = 0; c < 4; ++c) {
                float2 f2 = unpack2(acc[r][c]);
                float val = (f2.x + f2.y) * SCALE_F;
                int sj = s0 + tx + 16 * c;
                if (sj > lim) val = -1e30f;
                sc[r][c] = val;
                mt[r] = fmaxf(mt[r], val);
            }
        }
        #pragma unroll
        for (int off = 1; off < 16; off <<= 1) {
            #pragma unroll
            for (int r = 0; r < 4; ++r)
                mt[r] = fmaxf(mt[r], __shfl_xor_sync(0xffffffffu, mt[r], off));
        }

        float mnew[4], rowsum[4], scalef[4];
        #pragma unroll
        for (int r = 0; r < 4; ++r) {
            float mold = s.m[i0 + r];
            mnew[r]   = fmaxf(mold, mt[r]);
            scalef[r] = __expf(mold - mnew[r]);
            float rs = 0.0f;
            #pragma unroll
            for (int c = 0; c < 4; ++c) {
                float p = __expf(sc[r][c] - mnew[r]);
                sc[r][c] = p;
                rs += p;
            }
            rowsum[r] = rs;
        }
        #pragma unroll
        for (int off = 1; off < 16; off <<= 1) {
            #pragma unroll
            for (int r = 0; r < 4; ++r)
                rowsum[r] += __shfl_xor_sync(0xffffffffu, rowsum[r], off);
        }

        if (tx == 0) {
            #pragma unroll
            for (int r = 0; r < 4; ++r) {
                s.m[i0 + r]     = mnew[r];
                s.l[i0 + r]     = s.l[i0 + r] * scalef[r] + rowsum[r];
                s.scale[i0 + r] = scalef[r];
            }
        }
        // write probabilities transposed: pt[j][i]
        #pragma unroll
        for (int c = 0; c < 4; ++c)
            #pragma unroll
            for (int r = 0; r < 4; ++r)
                s.pt[tx + 16 * c][i0 + r] = sc[r][c];

        __syncthreads();

        // ---- phase 2: O = O*scale + P V, f32x2 paired over d ----
        #pragma unroll
        for (int r = 0; r < 4; ++r) {
            float sf = s.scale[i0 + r];
            unsigned long long sf2 = pack2(sf, sf);
            #pragma unroll
            for (int c = 0; c < 4; ++c)
                oacc[r][c] = mul2(oacc[r][c], sf2);
        }
        #pragma unroll 2
        for (int j = 0; j < TK; ++j) {
            float4 p4 = *reinterpret_cast<const float4*>(&s.pt[j][i0]);
            unsigned long long pr[4];
            pr[0] = pack2(p4.x, p4.x);
            pr[1] = pack2(p4.y, p4.y);
            pr[2] = pack2(p4.z, p4.z);
            pr[3] = pack2(p4.w, p4.w);
            #pragma unroll
            for (int sg = 0; sg < 4; ++sg) {
                unsigned long long vv =
                    *reinterpret_cast<const unsigned long long*>(&s.v[j][tx * 2 + sg * 32]);
                #pragma unroll
                for (int r = 0; r < 4; ++r)
                    ffma2(oacc[r][sg], pr[r], vv);
            }
        }
    }

    // ---- epilogue: divide by l, store ----
    float inv[4];
    #pragma unroll
    for (int r = 0; r < 4; ++r) inv[r] = 1.0f / s.l[i0 + r];

    #pragma unroll
    for (int r = 0; r < 4; ++r) {
        const int e = e0 + i0 + r;
        float* orow = out + (size_t)(b * CE + e) * (CH * CD) + h * CD;
        #pragma unroll
        for (int sg = 0; sg < 4; ++sg) {
            float2 f2 = unpack2(oacc[r][sg]);
            f2.x *= inv[r];
            f2.y *= inv[r];
            *reinterpret_cast<float2*>(orow + tx * 2 + sg * 32) = f2;
        }
    }
}

extern "C" void kernel_launch(void* const* d_in, const int* in_sizes, int n_in,
                              void* d_out, int out_size) {
    (void)in_sizes; (void)n_in; (void)out_size;
    const float* q  = (const float*)d_in[0];
    const float* k  = (const float*)d_in[1];
    const float* v  = (const float*)d_in[2];
    const float* kc = (const float*)d_in[3];
    const float* vc = (const float*)d_in[4];
    float* out = (float*)d_out;

    static_assert(sizeof(Smem) < 160 * 1024, "smem too big");
    cudaFuncSetAttribute(radix_extend_kernel,
                         cudaFuncAttributeMaxDynamicSharedMemorySize,
                         (int)sizeof(Smem));

    dim3 grid(CE / TQ, CH, CB);   // (8, 32, 4)
    radix_extend_kernel<<<grid, NTHREADS, sizeof(Smem)>>>(q, k, v, kc, vc, out);
}

// round 2
// speedup vs baseline: 1.0007x; 1.0007x over previous
#include <cuda_runtime.h>
#include <cstdint>
#include <cstddef>

#define CB 4
#define CE 512
#define CP 1536
#define CH 32
#define CHK 8
#define CD 128
#define TQ 64
#define TK 64
#define NTHREADS 256
#define QPAD 132
#define KPAD 132
#define VPAD 128
#define PPAD 68
#define SCALE_F 0.08838834764831845f

struct __align__(16) Smem {
    float q[TQ][QPAD];
    float k[TK][KPAD];
    float v[TK][VPAD];
    float pt[TK][PPAD];   // transposed probabilities: pt[j][i]
    float m[TQ];
    float l[TQ];
    float scale[TQ];
};

// ---- packed f32x2 helpers (Blackwell sm_103a) ----
__device__ __forceinline__ void ffma2(unsigned long long& d,
                                      unsigned long long a,
                                      unsigned long long b) {
    asm("fma.rn.f32x2 %0, %1, %2, %0;" : "+l"(d) : "l"(a), "l"(b));
}
__device__ __forceinline__ unsigned long long mul2(unsigned long long a,
                                                   unsigned long long b) {
    unsigned long long d;
    asm("mul.rn.f32x2 %0, %1, %2;" : "=l"(d) : "l"(a), "l"(b));
    return d;
}
__device__ __forceinline__ unsigned long long pack2(float lo, float hi) {
    unsigned long long d;
    asm("mov.b64 %0, {%1, %2};" : "=l"(d) : "f"(lo), "f"(hi));
    return d;
}
__device__ __forceinline__ float2 unpack2(unsigned long long p) {
    float2 f;
    asm("mov.b64 {%0, %1}, %2;" : "=f"(f.x), "=f"(f.y) : "l"(p));
    return f;
}

__global__ __launch_bounds__(NTHREADS, 1)
void radix_extend_kernel(const float* __restrict__ q,
                         const float* __restrict__ k,
                         const float* __restrict__ v,
                         const float* __restrict__ kc,
                         const float* __restrict__ vc,
                         float* __restrict__ out) {
    extern __shared__ Smem smem_buf[];
    Smem& s = smem_buf[0];

    const int t  = threadIdx.x;
    const int e0 = blockIdx.x * TQ;
    const int h  = blockIdx.y;
    const int b  = blockIdx.z;
    const int kh = h >> 2;   // GQA group size 4

    // ---- load Q tile, row-major flat copy (coalesced) ----
    {
        const float* qbase = q + ((size_t)(b * CE + e0) * CH + h) * CD;
        #pragma unroll
        for (int u = 0; u < 8; ++u) {
            int f  = t + u * NTHREADS;     // 0..2047
            int i  = f >> 5;               // row within tile
            int d4 = (f & 31) * 4;
            float4 val = *reinterpret_cast<const float4*>(qbase + (size_t)i * (CH * CD) + d4);
            *reinterpret_cast<float4*>(&s.q[i][d4]) = val;
        }
    }
    if (t < TQ) { s.m[t] = -1e30f; s.l[t] = 0.0f; }

    const int tx = t & 15;       // column-group lane (phase 1) / d-group (phase 2)
    const int ty = t >> 4;
    const int i0 = ty * 4;       // 4 query rows owned by this thread (both phases)

    // output accumulators: 4 rows x 4 d-pairs, d = 2*tx + 32*sg (+1)
    unsigned long long oacc[4][4];
    #pragma unroll
    for (int r = 0; r < 4; ++r)
        #pragma unroll
        for (int c = 0; c < 4; ++c) oacc[r][c] = 0ull;

    const int ntiles = (CP + e0 + TQ) / TK;

    for (int kt = 0; kt < ntiles; ++kt) {
        const int s0 = kt * TK;
        __syncthreads();   // previous phase-2 done with s.v / s.pt, phase-1 done with s.k

        // ---- load K/V tile (coalesced, conflict-free STS.128) ----
        #pragma unroll
        for (int u = 0; u < 8; ++u) {
            int f  = t + u * NTHREADS;
            int j  = f >> 5;
            int d4 = (f & 31) * 4;
            int sj = s0 + j;
            const float* krow;
            const float* vrow;
            if (sj < CP) {
                size_t off = ((size_t)(b * CP + sj) * CHK + kh) * CD;
                krow = kc + off; vrow = vc + off;
            } else {
                size_t off = ((size_t)(b * CE + (sj - CP)) * CHK + kh) * CD;
                krow = k + off;  vrow = v + off;
            }
            *reinterpret_cast<float4*>(&s.k[j][d4]) = *reinterpret_cast<const float4*>(krow + d4);
            *reinterpret_cast<float4*>(&s.v[j][d4]) = *reinterpret_cast<const float4*>(vrow + d4);
        }
        __syncthreads();

        // ---- phase 1: S = Q K^T, f32x2 paired over d ----
        // thread owns rows i0..i0+3, cols j = tx + 16*c (c = 0..3)
        unsigned long long acc[4][4];
        #pragma unroll
        for (int r = 0; r < 4; ++r)
            #pragma unroll
            for (int c = 0; c < 4; ++c) acc[r][c] = 0ull;

        #pragma unroll 2
        for (int d4 = 0; d4 < CD; d4 += 4) {
            unsigned long long qv[4][2], kv[4][2];
            #pragma unroll
            for (int r = 0; r < 4; ++r) {
                const ulonglong2 tmp = *reinterpret_cast<const ulonglong2*>(&s.q[i0 + r][d4]);
                qv[r][0] = tmp.x; qv[r][1] = tmp.y;
            }
            #pragma unroll
            for (int c = 0; c < 4; ++c) {
                const ulonglong2 tmp = *reinterpret_cast<const ulonglong2*>(&s.k[tx + 16 * c][d4]);
                kv[c][0] = tmp.x; kv[c][1] = tmp.y;
            }
            #pragma unroll
            for (int r = 0; r < 4; ++r)
                #pragma unroll
                for (int c = 0; c < 4; ++c) {
                    ffma2(acc[r][c], qv[r][0], kv[c][0]);
                    ffma2(acc[r][c], qv[r][1], kv[c][1]);
                }
        }

        // ---- finalize scores, mask, online softmax ----
        float sc[4][4];
        float mt[4];
        #pragma unroll
        for (int r = 0; r < 4; ++r) {
            mt[r] = -1e30f;
            const int lim = CP + e0 + i0 + r;    // key s visible iff s <= lim
            #pragma unroll
            for (int c = 0; c < 4; ++c) {
                float2 f2 = unpack2(acc[r][c]);
                float val = (f2.x + f2.y) * SCALE_F;
                int sj = s0 + tx + 16 * c;
                if (sj > lim) val = -1e30f;
                sc[r][c] = val;
                mt[r] = fmaxf(mt[r], val);
            }
        }
        #pragma unroll
        for (int off = 1; off < 16; off <<= 1) {
            #pragma unroll
            for (int r = 0; r < 4; ++r)
                mt[r] = fmaxf(mt[r], __shfl_xor_sync(0xffffffffu, mt[r], off));
        }

        float mnew[4], rowsum[4], scalef[4];
        #pragma unroll
        for (int r = 0; r < 4; ++r) {
            float mold = s.m[i0 + r];
            mnew[r]   = fmaxf(mold, mt[r]);
            scalef[r] = __expf(mold - mnew[r]);
            float rs = 0.0f;
            #pragma unroll
            for (int c = 0; c < 4; ++c) {
                float p = __expf(sc[r][c] - mnew[r]);
                sc[r][c] = p;
                rs += p;
            }
            rowsum[r] = rs;
        }
        #pragma unroll
        for (int off = 1; off < 16; off <<= 1) {
            #pragma unroll
            for (int r = 0; r < 4; ++r)
                rowsum[r] += __shfl_xor_sync(0xffffffffu, rowsum[r], off);
        }

        if (tx == 0) {
            #pragma unroll
            for (int r = 0; r < 4; ++r) {
                s.m[i0 + r]     = mnew[r];
                s.l[i0 + r]     = s.l[i0 + r] * scalef[r] + rowsum[r];
                s.scale[i0 + r] = scalef[r];
            }
        }
        // write probabilities transposed: pt[j][i]
        #pragma unroll
        for (int c = 0; c < 4; ++c)
            #pragma unroll
            for (int r = 0; r < 4; ++r)
                s.pt[tx + 16 * c][i0 + r] = sc[r][c];

        __syncthreads();

        // ---- phase 2: O = O*scale + P V, f32x2 paired over d ----
        #pragma unroll
        for (int r = 0; r < 4; ++r) {
            float sf = s.scale[i0 + r];
            unsigned long long sf2 = pack2(sf, sf);
            #pragma unroll
            for (int c = 0; c < 4; ++c)
                oacc[r][c] = mul2(oacc[r][c], sf2);
        }
        #pragma unroll 2
        for (int j = 0; j < TK; ++j) {
            float4 p4 = *reinterpret_cast<const float4*>(&s.pt[j][i0]);
            unsigned long long pr[4];
            pr[0] = pack2(p4.x, p4.x);
            pr[1] = pack2(p4.y, p4.y);
            pr[2] = pack2(p4.z, p4.z);
            pr[3] = pack2(p4.w, p4.w);
            #pragma unroll
            for (int sg = 0; sg < 4; ++sg) {
                unsigned long long vv =
                    *reinterpret_cast<const unsigned long long*>(&s.v[j][tx * 2 + sg * 32]);
                #pragma unroll
                for (int r = 0; r < 4; ++r)
                    ffma2(oacc[r][sg], pr[r], vv);
            }
        }
    }

    // ---- epilogue: divide by l, store ----
    float inv[4];
    #pragma unroll
    for (int r = 0; r < 4; ++r) inv[r] = 1.0f / s.l[i0 + r];

    #pragma unroll
    for (int r = 0; r < 4; ++r) {
        const int e = e0 + i0 + r;
        float* orow = out + (size_t)(b * CE + e) * (CH * CD) + h * CD;
        #pragma unroll
        for (int sg = 0; sg < 4; ++sg) {
            float2 f2 = unpack2(oacc[r][sg]);
            f2.x *= inv[r];
            f2.y *= inv[r];
            *reinterpret_cast<float2*>(orow + tx * 2 + sg * 32) = f2;
        }
    }
}

extern "C" void kernel_launch(void* const* d_in, const int* in_sizes, int n_in,
                              void* d_out, int out_size) {
    (void)in_sizes; (void)n_in; (void)out_size;
    const float* q  = (const float*)d_in[0];
    const float* k  = (const float*)d_in[1];
    const float* v  = (const float*)d_in[2];
    const float* kc = (const float*)d_in[3];
    const float* vc = (const float*)d_in[4];
    float* out = (float*)d_out;

    static_assert(sizeof(Smem) < 160 * 1024, "smem too big");
    cudaFuncSetAttribute(radix_extend_kernel,
                         cudaFuncAttributeMaxDynamicSharedMemorySize,
                         (int)sizeof(Smem));

    dim3 grid(CE / TQ, CH, CB);   // (8, 32, 4)
    radix_extend_kernel<<<grid, NTHREADS, sizeof(Smem)>>>(q, k, v, kc, vc, out);
}

// round 3
// speedup vs baseline: 1.2011x; 1.2002x over previous
#include <cuda_runtime.h>
#include <cstdint>
#include <cstddef>

#define CB 4
#define CE 512
#define CP 1536
#define CH 32
#define CHK 8
#define CD 128
#define TQ 128
#define TK 128
#define NTHREADS 256
#define QTS 132   // qT row stride (floats)
#define KS 132    // kpt row stride (floats)
#define VS 128
#define SCALE_F 0.08838834764831845f

struct __align__(16) Smem {
    float qT[CD][QTS];    // qT[d][i]  (transposed Q tile)
    float kpt[TK][KS];    // K tile, later overwritten by P^T (pt[j][i])
    float v[TK][VS];
};

// ---- packed f32x2 helpers (Blackwell sm_103a) ----
__device__ __forceinline__ void ffma2(unsigned long long& d,
                                      unsigned long long a,
                                      unsigned long long b) {
    asm("fma.rn.f32x2 %0, %1, %2, %0;" : "+l"(d) : "l"(a), "l"(b));
}
__device__ __forceinline__ unsigned long long mul2(unsigned long long a,
                                                   unsigned long long b) {
    unsigned long long d;
    asm("mul.rn.f32x2 %0, %1, %2;" : "=l"(d) : "l"(a), "l"(b));
    return d;
}
__device__ __forceinline__ unsigned long long pack2(float lo, float hi) {
    unsigned long long d;
    asm("mov.b64 %0, {%1, %2};" : "=l"(d) : "f"(lo), "f"(hi));
    return d;
}
__device__ __forceinline__ float2 unpack2(unsigned long long p) {
    float2 f;
    asm("mov.b64 {%0, %1}, %2;" : "=f"(f.x), "=f"(f.y) : "l"(p));
    return f;
}

__global__ __launch_bounds__(NTHREADS, 1)
void radix_extend_kernel(const float* __restrict__ gq,
                         const float* __restrict__ gk,
                         const float* __restrict__ gv,
                         const float* __restrict__ gkc,
                         const float* __restrict__ gvc,
                         float* __restrict__ out) {
    extern __shared__ Smem smem_buf[];
    Smem& s = smem_buf[0];

    const int t  = threadIdx.x;
    const int e0 = blockIdx.x * TQ;
    const int h  = blockIdx.y;
    const int b  = blockIdx.z;
    const int kh = h >> 2;   // GQA group size 4

    // ---- load Q transposed: qT[d][i] ----
    {
        const int i = t & 127;
        const int half = t >> 7;
        const float* qrow = gq + ((size_t)(b * CE + e0 + i) * CH + h) * CD;
        #pragma unroll
        for (int u = 0; u < 16; ++u) {
            int d4 = (half + 2 * u) * 4;   // 0..124
            float4 val = *reinterpret_cast<const float4*>(qrow + d4);
            s.qT[d4 + 0][i] = val.x;
            s.qT[d4 + 1][i] = val.y;
            s.qT[d4 + 2][i] = val.z;
            s.qT[d4 + 3][i] = val.w;
        }
    }

    const int rg = t >> 4;        // row group (half-warp): rows i0..i0+7
    const int cg = t & 15;        // phase-1 column lane / phase-2 d-slice lane
    const int i0 = rg * 8;

    // softmax running state, replicated across the 16 cg lanes of each row group
    float m_run[8], l_run[8];
    #pragma unroll
    for (int r = 0; r < 8; ++r) { m_run[r] = -1e30f; l_run[r] = 0.0f; }

    // output accumulators: 8 rows x 4 d-pairs (f32x2 over d), d = 2*cg + 32*dp (+1)
    unsigned long long oacc[8][4];
    #pragma unroll
    for (int r = 0; r < 8; ++r)
        #pragma unroll
        for (int dp = 0; dp < 4; ++dp) oacc[r][dp] = 0ull;

    const int ntiles = (CP + e0 + TQ) / TK;
    const int d4l    = (t & 31) * 4;   // K/V load lane d-offset
    const int jbase  = t >> 5;

    for (int kt = 0; kt < ntiles; ++kt) {
        const int s0 = kt * TK;
        __syncthreads();   // prev phase-2 done with v / pt

        // ---- load K/V tile (coalesced LDG.128 -> STS.128) ----
        #pragma unroll
        for (int u = 0; u < 16; ++u) {
            int j  = jbase + 8 * u;
            int sj = s0 + j;
            const float* kr;
            const float* vr;
            if (sj < CP) {
                size_t off = ((size_t)(b * CP + sj) * CHK + kh) * CD;
                kr = gkc + off; vr = gvc + off;
            } else {
                size_t off = ((size_t)(b * CE + (sj - CP)) * CHK + kh) * CD;
                kr = gk + off;  vr = gv + off;
            }
            *reinterpret_cast<float4*>(&s.kpt[j][d4l]) = *reinterpret_cast<const float4*>(kr + d4l);
            *reinterpret_cast<float4*>(&s.v[j][d4l])   = *reinterpret_cast<const float4*>(vr + d4l);
        }
        __syncthreads();

        // ---- phase 1: S = Q K^T ----
        // acc[rp][cc]: f32x2 = rows (i0+2rp, i0+2rp+1), col j = cg + 16*cc
        unsigned long long acc[4][8];
        #pragma unroll
        for (int rp = 0; rp < 4; ++rp)
            #pragma unroll
            for (int cc = 0; cc < 8; ++cc) acc[rp][cc] = 0ull;

        #pragma unroll 1
        for (int d4 = 0; d4 < CD; d4 += 4) {
            unsigned long long qp[4][4];   // [dd][rp]
            #pragma unroll
            for (int dd = 0; dd < 4; ++dd) {
                ulonglong2 a  = *reinterpret_cast<const ulonglong2*>(&s.qT[d4 + dd][i0]);
                ulonglong2 b2 = *reinterpret_cast<const ulonglong2*>(&s.qT[d4 + dd][i0 + 4]);
                qp[dd][0] = a.x;  qp[dd][1] = a.y;
                qp[dd][2] = b2.x; qp[dd][3] = b2.y;
            }
            #pragma unroll
            for (int cc = 0; cc < 8; ++cc) {
                float4 kf = *reinterpret_cast<const float4*>(&s.kpt[cg + 16 * cc][d4]);
                unsigned long long kd;
                kd = pack2(kf.x, kf.x);
                ffma2(acc[0][cc], qp[0][0], kd); ffma2(acc[1][cc], qp[0][1], kd);
                ffma2(acc[2][cc], qp[0][2], kd); ffma2(acc[3][cc], qp[0][3], kd);
                kd = pack2(kf.y, kf.y);
                ffma2(acc[0][cc], qp[1][0], kd); ffma2(acc[1][cc], qp[1][1], kd);
                ffma2(acc[2][cc], qp[1][2], kd); ffma2(acc[3][cc], qp[1][3], kd);
                kd = pack2(kf.z, kf.z);
                ffma2(acc[0][cc], qp[2][0], kd); ffma2(acc[1][cc], qp[2][1], kd);
                ffma2(acc[2][cc], qp[2][2], kd); ffma2(acc[3][cc], qp[2][3], kd);
                kd = pack2(kf.w, kf.w);
                ffma2(acc[0][cc], qp[3][0], kd); ffma2(acc[1][cc], qp[3][1], kd);
                ffma2(acc[2][cc], qp[3][2], kd); ffma2(acc[3][cc], qp[3][3], kd);
            }
        }

        // ---- mask + scale + online softmax (register-resident m/l) ----
        float mrow[8];
        #pragma unroll
        for (int r = 0; r < 8; ++r) mrow[r] = -1e30f;

        #pragma unroll
        for (int rp = 0; rp < 4; ++rp) {
            const int lim = CP + e0 + i0 + 2 * rp;   // lo row limit; hi row = lim+1
            #pragma unroll
            for (int cc = 0; cc < 8; ++cc) {
                float2 f = unpack2(acc[rp][cc]);
                int sj = s0 + cg + 16 * cc;
                float lo = (sj <= lim)     ? f.x * SCALE_F : -1e30f;
                float hi = (sj <= lim + 1) ? f.y * SCALE_F : -1e30f;
                acc[rp][cc] = pack2(lo, hi);
                mrow[2 * rp]     = fmaxf(mrow[2 * rp], lo);
                mrow[2 * rp + 1] = fmaxf(mrow[2 * rp + 1], hi);
            }
        }
        #pragma unroll
        for (int off = 1; off < 16; off <<= 1)
            #pragma unroll
            for (int r = 0; r < 8; ++r)
                mrow[r] = fmaxf(mrow[r], __shfl_xor_sync(0xffffffffu, mrow[r], off));

        float mnew[8], scf[8], psum[8];
        #pragma unroll
        for (int r = 0; r < 8; ++r) {
            mnew[r] = fmaxf(m_run[r], mrow[r]);
            scf[r]  = __expf(m_run[r] - mnew[r]);
            psum[r] = 0.0f;
        }
        #pragma unroll
        for (int rp = 0; rp < 4; ++rp) {
            #pragma unroll
            for (int cc = 0; cc < 8; ++cc) {
                float2 f = unpack2(acc[rp][cc]);
                float plo = __expf(f.x - mnew[2 * rp]);
                float phi = __expf(f.y - mnew[2 * rp + 1]);
                acc[rp][cc] = pack2(plo, phi);
                psum[2 * rp]     += plo;
                psum[2 * rp + 1] += phi;
            }
        }
        #pragma unroll
        for (int off = 1; off < 16; off <<= 1)
            #pragma unroll
            for (int r = 0; r < 8; ++r)
                psum[r] += __shfl_xor_sync(0xffffffffu, psum[r], off);
        #pragma unroll
        for (int r = 0; r < 8; ++r) {
            l_run[r] = l_run[r] * scf[r] + psum[r];
            m_run[r] = mnew[r];
        }

        __syncthreads();   // all K reads done -> safe to overwrite kpt with P^T

        // ---- write P^T: pt[j][i] (row pairs packed) ----
        #pragma unroll
        for (int rp = 0; rp < 4; ++rp)
            #pragma unroll
            for (int cc = 0; cc < 8; ++cc)
                *reinterpret_cast<unsigned long long*>(&s.kpt[cg + 16 * cc][i0 + 2 * rp]) = acc[rp][cc];
        __syncthreads();

        // ---- phase 2: O = O*scf + P V  (d = 2*cg + 32*dp) ----
        #pragma unroll
        for (int r = 0; r < 8; ++r) {
            unsigned long long sf2 = pack2(scf[r], scf[r]);
            #pragma unroll
            for (int dp = 0; dp < 4; ++dp)
                oacc[r][dp] = mul2(oacc[r][dp], sf2);
        }
        #pragma unroll 2
        for (int j = 0; j < TK; ++j) {
            float4 pa = *reinterpret_cast<const float4*>(&s.kpt[j][i0]);
            float4 pb = *reinterpret_cast<const float4*>(&s.kpt[j][i0 + 4]);
            unsigned long long pr[8];
            pr[0] = pack2(pa.x, pa.x); pr[1] = pack2(pa.y, pa.y);
            pr[2] = pack2(pa.z, pa.z); pr[3] = pack2(pa.w, pa.w);
            pr[4] = pack2(pb.x, pb.x); pr[5] = pack2(pb.y, pb.y);
            pr[6] = pack2(pb.z, pb.z); pr[7] = pack2(pb.w, pb.w);
            #pragma unroll
            for (int dp = 0; dp < 4; ++dp) {
                unsigned long long vv =
                    *reinterpret_cast<const unsigned long long*>(&s.v[j][2 * cg + 32 * dp]);
                #pragma unroll
                for (int r = 0; r < 8; ++r)
                    ffma2(oacc[r][dp], pr[r], vv);
            }
        }
    }

    // ---- epilogue: divide by l, store ----
    #pragma unroll
    for (int r = 0; r < 8; ++r) {
        const int e = e0 + i0 + r;
        float* orow = out + (size_t)(b * CE + e) * (CH * CD) + h * CD;
        float inv = 1.0f / l_run[r];
        #pragma unroll
        for (int dp = 0; dp < 4; ++dp) {
            float2 f2 = unpack2(oacc[r][dp]);
            f2.x *= inv;
            f2.y *= inv;
            *reinterpret_cast<float2*>(orow + 2 * cg + 32 * dp) = f2;
        }
    }
}

extern "C" void kernel_launch(void* const* d_in, const int* in_sizes, int n_in,
                              void* d_out, int out_size) {
    (void)in_sizes; (void)n_in; (void)out_size;
    const float* q  = (const float*)d_in[0];
    const float* k  = (const float*)d_in[1];
    const float* v  = (const float*)d_in[2];
    const float* kc = (const float*)d_in[3];
    const float* vc = (const float*)d_in[4];
    float* out = (float*)d_out;

    static_assert(sizeof(Smem) <= 227 * 1024, "smem too big");
    cudaFuncSetAttribute(radix_extend_kernel,
                         cudaFuncAttributeMaxDynamicSharedMemorySize,
                         (int)sizeof(Smem));

    dim3 grid(CE / TQ, CH, CB);   // (4, 32, 4) = 512 CTAs
    radix_extend_kernel<<<grid, NTHREADS, sizeof(Smem)>>>(q, k, v, kc, vc, out);
}

// round 5
// speedup vs baseline: 2.0751x; 1.7276x over previous
#include <cuda_runtime.h>
#include <cstdint>
#include <cstddef>

#define CB 4
#define CE 512
#define CP 1536
#define CH 32
#define CHK 8
#define CD 128
#define TQ 128
#define TK 64
#define NTHREADS 256
#define SCALE_F 0.08838834764831845f
#define NEG_INF -1e30f

// smem byte offsets: bf16 planes, 256B per row (128 bf16), XOR-swizzled
#define OFF_QH 0
#define OFF_QL 32768
#define OFF_KH 65536
#define OFF_KL 81920
#define OFF_VH 98304
#define OFF_VL 114688
#define SMEM_BYTES 131072

// swizzled byte offset: row stride 256B, 16B granule xor'ed with row&7
__device__ __forceinline__ uint32_t swz(uint32_t row, uint32_t byteCol) {
    return (row << 8) + (byteCol ^ ((row & 7) << 4));
}

__device__ __forceinline__ uint32_t smem_u32(const void* p) {
    uint32_t a;
    asm("{ .reg .u64 t; cvta.to.shared.u64 t, %1; cvt.u32.u64 %0, t; }"
        : "=r"(a) : "l"(p));
    return a;
}

// split pair of floats into bf16x2 hi (rn) + bf16x2 lo (residual)
__device__ __forceinline__ void split2(float x0, float x1,
                                       uint32_t& hp, uint32_t& lp) {
    asm("cvt.rn.bf16x2.f32 %0, %1, %2;" : "=r"(hp) : "f"(x1), "f"(x0));
    float h0 = __uint_as_float(hp << 16);
    float h1 = __uint_as_float(hp & 0xffff0000u);
    float l0 = x0 - h0;
    float l1 = x1 - h1;
    asm("cvt.rn.bf16x2.f32 %0, %1, %2;" : "=r"(lp) : "f"(l1), "f"(l0));
}

__device__ __forceinline__ void pack_bf16(float x0, float x1, uint32_t& hp) {
    asm("cvt.rn.bf16x2.f32 %0, %1, %2;" : "=r"(hp) : "f"(x1), "f"(x0));
}

__device__ __forceinline__ void ldsm4(uint32_t r[4], uint32_t addr) {
    asm volatile("ldmatrix.sync.aligned.m8n8.x4.shared.b16 {%0,%1,%2,%3}, [%4];"
                 : "=r"(r[0]), "=r"(r[1]), "=r"(r[2]), "=r"(r[3]) : "r"(addr));
}
__device__ __forceinline__ void ldsm4t(uint32_t r[4], uint32_t addr) {
    asm volatile("ldmatrix.sync.aligned.m8n8.x4.trans.shared.b16 {%0,%1,%2,%3}, [%4];"
                 : "=r"(r[0]), "=r"(r[1]), "=r"(r[2]), "=r"(r[3]) : "r"(addr));
}

__device__ __forceinline__ void mma16816(float c[4], const uint32_t a[4],
                                         uint32_t b0, uint32_t b1) {
    asm volatile(
        "mma.sync.aligned.m16n8k16.row.col.f32.bf16.bf16.f32 "
        "{%0,%1,%2,%3}, {%4,%5,%6,%7}, {%8,%9}, {%0,%1,%2,%3};"
        : "+f"(c[0]), "+f"(c[1]), "+f"(c[2]), "+f"(c[3])
        : "r"(a[0]), "r"(a[1]), "r"(a[2]), "r"(a[3]), "r"(b0), "r"(b1));
}

__global__ __launch_bounds__(NTHREADS, 1)
void radix_extend_hmma(const float* __restrict__ gq,
                       const float* __restrict__ gk,
                       const float* __restrict__ gv,
                       const float* __restrict__ gkc,
                       const float* __restrict__ gvc,
                       float* __restrict__ out) {
    extern __shared__ char smem[];
    const uint32_t sb = smem_u32(smem);
    const int t = threadIdx.x, w = t >> 5, lane = t & 31;
    const int e0 = blockIdx.x * TQ, h = blockIdx.y, b = blockIdx.z;
    const int kh = h >> 2;   // GQA group 4

    // ---- load Q tile: fold scale, split bf16, swizzled store ----
    {
        const int qrow = t >> 1;
        const int cbase = (t & 1) * 64;
        const float* qr = gq + ((size_t)(b * CE + e0 + qrow) * CH + h) * CD;
        #pragma unroll
        for (int g = 0; g < 8; ++g) {
            int colf = cbase + 8 * g;
            float4 x0 = *(const float4*)(qr + colf);
            float4 x1 = *(const float4*)(qr + colf + 4);
            x0.x *= SCALE_F; x0.y *= SCALE_F; x0.z *= SCALE_F; x0.w *= SCALE_F;
            x1.x *= SCALE_F; x1.y *= SCALE_F; x1.z *= SCALE_F; x1.w *= SCALE_F;
            uint4 hi, lo;
            split2(x0.x, x0.y, hi.x, lo.x);
            split2(x0.z, x0.w, hi.y, lo.y);
            split2(x1.x, x1.y, hi.z, lo.z);
            split2(x1.z, x1.w, hi.w, lo.w);
            uint32_t off = swz(qrow, (uint32_t)colf * 2);
            *(uint4*)(smem + OFF_QH + off) = hi;
            *(uint4*)(smem + OFF_QL + off) = lo;
        }
    }
    __syncthreads();

    // ---- extract persistent Q fragments (A m16k16, hi/lo) ----
    uint32_t qh[8][4], ql[8][4];
    {
        const uint32_t qrow = 16 * w + (lane & 7) + 8 * ((lane >> 3) & 1);
        const uint32_t qbc0 = 16 * (lane >> 4);
        #pragma unroll
        for (int kk = 0; kk < 8; ++kk) {
            uint32_t off = swz(qrow, qbc0 + kk * 32);
            ldsm4(qh[kk], sb + OFF_QH + off);
            ldsm4(ql[kk], sb + OFF_QL + off);
        }
    }

    // per-thread fragment lane pieces
    const uint32_t rB  = (lane & 7) + 8 * (lane >> 4);          // K frag row-in-group
    const uint32_t bcB = 16 * ((lane >> 3) & 1);                // K frag byteCol part
    const uint32_t rV  = (lane & 7) + 8 * ((lane >> 3) & 1);    // V frag row-in-group
    const uint32_t bcV = 16 * (lane >> 4);                      // V frag byteCol part

    // softmax state (rows r0 = 16w + lane/4, r1 = r0 + 8)
    const int row0 = 16 * w + (lane >> 2);
    const int lim0 = CP + e0 + row0;       // visibility limit row0
    const int lim1 = lim0 + 8;             // row1
    float m0 = NEG_INF, m1 = NEG_INF, l0 = 0.0f, l1 = 0.0f;

    float o[16][4];
    #pragma unroll
    for (int j = 0; j < 16; ++j)
        #pragma unroll
        for (int c = 0; c < 4; ++c) o[j][c] = 0.0f;

    const int ntiles = (CP + e0 + TQ) / TK;
    // K/V loader indices
    const int lrow = t >> 2;
    const int lc   = (t & 3) * 32;

    for (int kt = 0; kt < ntiles; ++kt) {
        const int s0 = kt * TK;
        __syncthreads();

        // ---- load K/V tile, split bf16, swizzled store ----
        {
            const int sj = s0 + lrow;
            const float *kr, *vr;
            if (sj < CP) {
                size_t off = ((size_t)(b * CP + sj) * CHK + kh) * CD;
                kr = gkc + off; vr = gvc + off;
            } else {
                size_t off = ((size_t)(b * CE + (sj - CP)) * CHK + kh) * CD;
                kr = gk + off; vr = gv + off;
            }
            #pragma unroll
            for (int g = 0; g < 4; ++g) {
                int colf = lc + 8 * g;
                uint32_t off = swz(lrow, (uint32_t)colf * 2);
                float4 x0 = *(const float4*)(kr + colf);
                float4 x1 = *(const float4*)(kr + colf + 4);
                uint4 hi, lo;
                split2(x0.x, x0.y, hi.x, lo.x);
                split2(x0.z, x0.w, hi.y, lo.y);
                split2(x1.x, x1.y, hi.z, lo.z);
                split2(x1.z, x1.w, hi.w, lo.w);
                *(uint4*)(smem + OFF_KH + off) = hi;
                *(uint4*)(smem + OFF_KL + off) = lo;
                x0 = *(const float4*)(vr + colf);
                x1 = *(const float4*)(vr + colf + 4);
                split2(x0.x, x0.y, hi.x, lo.x);
                split2(x0.z, x0.w, hi.y, lo.y);
                split2(x1.x, x1.y, hi.z, lo.z);
                split2(x1.z, x1.w, hi.w, lo.w);
                *(uint4*)(smem + OFF_VH + off) = hi;
                *(uint4*)(smem + OFF_VL + off) = lo;
            }
        }
        __syncthreads();

        // ---- phase 1: S = Q K^T  (3-way split on HMMA) ----
        float s[8][4];
        #pragma unroll
        for (int nt = 0; nt < 8; ++nt)
            #pragma unroll
            for (int c = 0; c < 4; ++c) s[nt][c] = 0.0f;

        #pragma unroll
        for (int kk = 0; kk < 8; ++kk) {
            #pragma unroll
            for (int ng = 0; ng < 4; ++ng) {
                uint32_t kh4[4], kl4[4];
                uint32_t off = swz(16 * ng + rB, bcB + kk * 32);
                ldsm4(kh4, sb + OFF_KH + off);
                ldsm4(kl4, sb + OFF_KL + off);
                mma16816(s[2 * ng],     qh[kk], kh4[0], kh4[1]);
                mma16816(s[2 * ng + 1], qh[kk], kh4[2], kh4[3]);
                mma16816(s[2 * ng],     ql[kk], kh4[0], kh4[1]);
                mma16816(s[2 * ng + 1], ql[kk], kh4[2], kh4[3]);
                mma16816(s[2 * ng],     qh[kk], kl4[0], kl4[1]);
                mma16816(s[2 * ng + 1], qh[kk], kl4[2], kl4[3]);
            }
        }

        // ---- mask (only last 2 tiles) ----
        if (s0 + TK - 1 > CP + e0) {
            const int j0 = s0 + 2 * (lane & 3);
            #pragma unroll
            for (int nt = 0; nt < 8; ++nt) {
                int jj = j0 + 8 * nt;
                if (jj     > lim0) s[nt][0] = NEG_INF;
                if (jj + 1 > lim0) s[nt][1] = NEG_INF;
                if (jj     > lim1) s[nt][2] = NEG_INF;
                if (jj + 1 > lim1) s[nt][3] = NEG_INF;
            }
        }

        // ---- online softmax (register state, quad reduction) ----
        float mt0 = NEG_INF, mt1 = NEG_INF;
        #pragma unroll
        for (int nt = 0; nt < 8; ++nt) {
            mt0 = fmaxf(mt0, fmaxf(s[nt][0], s[nt][1]));
            mt1 = fmaxf(mt1, fmaxf(s[nt][2], s[nt][3]));
        }
        mt0 = fmaxf(mt0, __shfl_xor_sync(0xffffffffu, mt0, 1));
        mt0 = fmaxf(mt0, __shfl_xor_sync(0xffffffffu, mt0, 2));
        mt1 = fmaxf(mt1, __shfl_xor_sync(0xffffffffu, mt1, 1));
        mt1 = fmaxf(mt1, __shfl_xor_sync(0xffffffffu, mt1, 2));

        float mn0 = fmaxf(m0, mt0), mn1 = fmaxf(m1, mt1);
        float sc0 = __expf(m0 - mn0), sc1 = __expf(m1 - mn1);
        m0 = mn0; m1 = mn1;

        float ps0 = 0.0f, ps1 = 0.0f;
        #pragma unroll
        for (int nt = 0; nt < 8; ++nt) {
            s[nt][0] = __expf(s[nt][0] - mn0);
            s[nt][1] = __expf(s[nt][1] - mn0);
            s[nt][2] = __expf(s[nt][2] - mn1);
            s[nt][3] = __expf(s[nt][3] - mn1);
            ps0 += s[nt][0] + s[nt][1];
            ps1 += s[nt][2] + s[nt][3];
        }
        ps0 += __shfl_xor_sync(0xffffffffu, ps0, 1);
        ps0 += __shfl_xor_sync(0xffffffffu, ps0, 2);
        ps1 += __shfl_xor_sync(0xffffffffu, ps1, 1);
        ps1 += __shfl_xor_sync(0xffffffffu, ps1, 2);
        l0 = l0 * sc0 + ps0;
        l1 = l1 * sc1 + ps1;

        // rescale O
        #pragma unroll
        for (int j = 0; j < 16; ++j) {
            o[j][0] *= sc0; o[j][1] *= sc0;
            o[j][2] *= sc1; o[j][3] *= sc1;
        }

        // ---- phase 2: O += P V  (3-way split on HMMA) ----
        #pragma unroll
        for (int kk = 0; kk < 4; ++kk) {
            uint32_t ah[4], al[4];
            split2(s[2 * kk][0],     s[2 * kk][1],     ah[0], al[0]);
            split2(s[2 * kk][2],     s[2 * kk][3],     ah[1], al[1]);
            split2(s[2 * kk + 1][0], s[2 * kk + 1][1], ah[2], al[2]);
            split2(s[2 * kk + 1][2], s[2 * kk + 1][3], ah[3], al[3]);
            #pragma unroll
            for (int ng = 0; ng < 8; ++ng) {
                uint32_t vh4[4], vl4[4];
                uint32_t off = swz(16 * kk + rV, bcV + 32 * ng);
                ldsm4t(vh4, sb + OFF_VH + off);
                ldsm4t(vl4, sb + OFF_VL + off);
                mma16816(o[2 * ng],     ah, vh4[0], vh4[1]);
                mma16816(o[2 * ng + 1], ah, vh4[2], vh4[3]);
                mma16816(o[2 * ng],     al, vh4[0], vh4[1]);
                mma16816(o[2 * ng + 1], al, vh4[2], vh4[3]);
                mma16816(o[2 * ng],     ah, vl4[0], vl4[1]);
                mma16816(o[2 * ng + 1], ah, vl4[2], vl4[3]);
            }
        }
    }

    // ---- epilogue: normalize by l, store ----
    const float inv0 = 1.0f / l0, inv1 = 1.0f / l1;
    float* orow0 = out + (size_t)(b * CE + e0 + row0) * (CH * CD) + h * CD;
    float* orow1 = orow0 + (size_t)8 * (CH * CD);
    const int dc = 2 * (lane & 3);
    #pragma unroll
    for (int j = 0; j < 16; ++j) {
        float2 f0 = make_float2(o[j][0] * inv0, o[j][1] * inv0);
        float2 f1 = make_float2(o[j][2] * inv1, o[j][3] * inv1);
        *(float2*)(orow0 + 8 * j + dc) = f0;
        *(float2*)(orow1 + 8 * j + dc) = f1;
    }
}

extern "C" void kernel_launch(void* const* d_in, const int* in_sizes, int n_in,
                              void* d_out, int out_size) {
    (void)in_sizes; (void)n_in; (void)out_size;
    const float* q  = (const float*)d_in[0];
    const float* k  = (const float*)d_in[1];
    const float* v  = (const float*)d_in[2];
    const float* kc = (const float*)d_in[3];
    const float* vc = (const float*)d_in[4];
    float* out = (float*)d_out;

    cudaFuncSetAttribute(radix_extend_hmma,
                         cudaFuncAttributeMaxDynamicSharedMemorySize, SMEM_BYTES);

    dim3 grid(CE / TQ, CH, CB);   // (4, 32, 4) = 512 CTAs
    radix_extend_hmma<<<grid, NTHREADS, SMEM_BYTES>>>(q, k, v, kc, vc, out);
}

// round 6
// speedup vs baseline: 3.2891x; 1.5851x over previous
#include <cuda_runtime.h>
#include <cstdint>
#include <cstddef>

#define CB 4
#define CE 512
#define CP 1536
#define CH 32
#define CHK 8
#define CD 128
#define CS 2048
#define TQ 128
#define TK 64
#define NTHREADS 256
#define SCALE_F 0.08838834764831845f
#define NEG_INF -1e30f

// scratch: bf16 planes in swizzled layout, 256B per row
#define SCR_PLANE (16u * 1024 * 1024)
__device__ __align__(256) unsigned char g_scr[4ull * SCR_PLANE];  // KH,KL,VH,VL

// smem: Q planes + 2-stage K/V buffers
#define OFF_QH 0
#define OFF_QL 32768
#define OFF_ST 65536
#define STAGE_STRIDE 65536
#define PLANE_STRIDE 16384
#define SMEM_BYTES 196608

// swizzled byte offset: row stride 256B, 16B granule xor'ed with row&7
__device__ __forceinline__ uint32_t swz(uint32_t row, uint32_t byteCol) {
    return (row << 8) + (byteCol ^ ((row & 7) << 4));
}

__device__ __forceinline__ uint32_t smem_u32(const void* p) {
    uint32_t a;
    asm("{ .reg .u64 t; cvta.to.shared.u64 t, %1; cvt.u32.u64 %0, t; }"
        : "=r"(a) : "l"(p));
    return a;
}

// split pair of floats into bf16x2 hi (rn) + bf16x2 lo (residual)
__device__ __forceinline__ void split2(float x0, float x1,
                                       uint32_t& hp, uint32_t& lp) {
    asm("cvt.rn.bf16x2.f32 %0, %1, %2;" : "=r"(hp) : "f"(x1), "f"(x0));
    float h0 = __uint_as_float(hp << 16);
    float h1 = __uint_as_float(hp & 0xffff0000u);
    float l0 = x0 - h0;
    float l1 = x1 - h1;
    asm("cvt.rn.bf16x2.f32 %0, %1, %2;" : "=r"(lp) : "f"(l1), "f"(l0));
}

__device__ __forceinline__ void ldsm4(uint32_t r[4], uint32_t addr) {
    asm volatile("ldmatrix.sync.aligned.m8n8.x4.shared.b16 {%0,%1,%2,%3}, [%4];"
                 : "=r"(r[0]), "=r"(r[1]), "=r"(r[2]), "=r"(r[3]) : "r"(addr));
}
__device__ __forceinline__ void ldsm4t(uint32_t r[4], uint32_t addr) {
    asm volatile("ldmatrix.sync.aligned.m8n8.x4.trans.shared.b16 {%0,%1,%2,%3}, [%4];"
                 : "=r"(r[0]), "=r"(r[1]), "=r"(r[2]), "=r"(r[3]) : "r"(addr));
}

__device__ __forceinline__ void mma16816(float c[4], const uint32_t a[4],
                                         uint32_t b0, uint32_t b1) {
    asm volatile(
        "mma.sync.aligned.m16n8k16.row.col.f32.bf16.bf16.f32 "
        "{%0,%1,%2,%3}, {%4,%5,%6,%7}, {%8,%9}, {%0,%1,%2,%3};"
        : "+f"(c[0]), "+f"(c[1]), "+f"(c[2]), "+f"(c[3])
        : "r"(a[0]), "r"(a[1]), "r"(a[2]), "r"(a[3]), "r"(b0), "r"(b1));
}

__device__ __forceinline__ void cpa16(uint32_t dst, const void* src) {
    asm volatile("cp.async.cg.shared.global [%0], [%1], 16;"
                 :: "r"(dst), "l"(src) : "memory");
}
#define CPA_COMMIT() asm volatile("cp.async.commit_group;" ::: "memory")
#define CPA_WAIT1()  asm volatile("cp.async.wait_group 1;" ::: "memory")

// ---------------- prep kernel: fp32 K/V -> swizzled bf16 hi/lo planes ----------------
__global__ __launch_bounds__(NTHREADS)
void prep_kv(const float* __restrict__ gk,  const float* __restrict__ gv,
             const float* __restrict__ gkc, const float* __restrict__ gvc) {
    const int task = blockIdx.x * NTHREADS + threadIdx.x;  // B*Hk*S*16 = 1048576
    const int g   = task & 15;
    const int s   = (task >> 4) & (CS - 1);
    const int khb = task >> 15;              // b*8 + kh, 0..31
    const int kh  = khb & 7, b = khb >> 3;

    const float *kr, *vr;
    if (s < CP) {
        size_t o = ((size_t)(b * CP + s) * CHK + kh) * CD;
        kr = gkc + o; vr = gvc + o;
    } else {
        size_t o = ((size_t)(b * CE + (s - CP)) * CHK + kh) * CD;
        kr = gk + o; vr = gv + o;
    }
    const int col = g * 8;
    const uint32_t dst = (((uint32_t)khb * CS + s) << 8) + ((g * 16) ^ ((s & 7) << 4));

    float4 x0, x1; uint4 hi, lo;
    x0 = *(const float4*)(kr + col); x1 = *(const float4*)(kr + col + 4);
    split2(x0.x, x0.y, hi.x, lo.x); split2(x0.z, x0.w, hi.y, lo.y);
    split2(x1.x, x1.y, hi.z, lo.z); split2(x1.z, x1.w, hi.w, lo.w);
    *(uint4*)(g_scr + 0ull * SCR_PLANE + dst) = hi;
    *(uint4*)(g_scr + 1ull * SCR_PLANE + dst) = lo;

    x0 = *(const float4*)(vr + col); x1 = *(const float4*)(vr + col + 4);
    split2(x0.x, x0.y, hi.x, lo.x); split2(x0.z, x0.w, hi.y, lo.y);
    split2(x1.x, x1.y, hi.z, lo.z); split2(x1.z, x1.w, hi.w, lo.w);
    *(uint4*)(g_scr + 2ull * SCR_PLANE + dst) = hi;
    *(uint4*)(g_scr + 3ull * SCR_PLANE + dst) = lo;
}

// ---------------- main attention kernel ----------------
__global__ __launch_bounds__(NTHREADS, 1)
void radix_extend_hmma(const float* __restrict__ gq, float* __restrict__ out) {
    extern __shared__ char smem[];
    const uint32_t sb = smem_u32(smem);
    const int t = threadIdx.x, w = t >> 5, lane = t & 31;
    const int e0 = blockIdx.x * TQ, h = blockIdx.y, b = blockIdx.z;
    const int khb = b * CHK + (h >> 2);
    const int ntiles = (CP + e0 + TQ) / TK;

    // prefetch tile 0 while we convert Q
    {
        const uint32_t tile_off = (((uint32_t)khb * CS) << 8);  // s0 = 0
        #pragma unroll
        for (int u = 0; u < 16; ++u) {
            int idx = u * NTHREADS + t;          // 0..4095
            int plane = idx >> 10;
            int off = (idx & 1023) * 16;
            cpa16(sb + OFF_ST + plane * PLANE_STRIDE + off,
                  g_scr + (size_t)plane * SCR_PLANE + tile_off + off);
        }
    }
    CPA_COMMIT();

    // ---- load Q tile: fold scale, split bf16, swizzled store ----
    {
        const int qrow = t >> 1;
        const int cbase = (t & 1) * 64;
        const float* qr = gq + ((size_t)(b * CE + e0 + qrow) * CH + h) * CD;
        #pragma unroll
        for (int g = 0; g < 8; ++g) {
            int colf = cbase + 8 * g;
            float4 x0 = *(const float4*)(qr + colf);
            float4 x1 = *(const float4*)(qr + colf + 4);
            x0.x *= SCALE_F; x0.y *= SCALE_F; x0.z *= SCALE_F; x0.w *= SCALE_F;
            x1.x *= SCALE_F; x1.y *= SCALE_F; x1.z *= SCALE_F; x1.w *= SCALE_F;
            uint4 hi, lo;
            split2(x0.x, x0.y, hi.x, lo.x);
            split2(x0.z, x0.w, hi.y, lo.y);
            split2(x1.x, x1.y, hi.z, lo.z);
            split2(x1.z, x1.w, hi.w, lo.w);
            uint32_t off = swz(qrow, (uint32_t)colf * 2);
            *(uint4*)(smem + OFF_QH + off) = hi;
            *(uint4*)(smem + OFF_QL + off) = lo;
        }
    }
    __syncthreads();

    // ---- persistent Q fragments (A m16k16, hi/lo) ----
    uint32_t qh[8][4], ql[8][4];
    {
        const uint32_t qrow = 16 * w + (lane & 7) + 8 * ((lane >> 3) & 1);
        const uint32_t qbc0 = 16 * (lane >> 4);
        #pragma unroll
        for (int kk = 0; kk < 8; ++kk) {
            uint32_t off = swz(qrow, qbc0 + kk * 32);
            ldsm4(qh[kk], sb + OFF_QH + off);
            ldsm4(ql[kk], sb + OFF_QL + off);
        }
    }

    const uint32_t rB  = (lane & 7) + 8 * (lane >> 4);
    const uint32_t bcB = 16 * ((lane >> 3) & 1);
    const uint32_t rV  = (lane & 7) + 8 * ((lane >> 3) & 1);
    const uint32_t bcV = 16 * (lane >> 4);

    const int row0 = 16 * w + (lane >> 2);
    const int lim0 = CP + e0 + row0;
    const int lim1 = lim0 + 8;
    float m0 = NEG_INF, m1 = NEG_INF, l0 = 0.0f, l1 = 0.0f;

    float o[16][4];
    #pragma unroll
    for (int j = 0; j < 16; ++j)
        #pragma unroll
        for (int c = 0; c < 4; ++c) o[j][c] = 0.0f;

    for (int kt = 0; kt < ntiles; ++kt) {
        const int s0 = kt * TK;
        const uint32_t stage = sb + OFF_ST + (kt & 1) * STAGE_STRIDE;

        __syncthreads();   // everyone done computing tile kt-1 (buffer reuse)

        // prefetch tile kt+1 into the other stage
        if (kt + 1 < ntiles) {
            const uint32_t tile_off = (((uint32_t)khb * CS + (s0 + TK)) << 8);
            const uint32_t dstb = sb + OFF_ST + ((kt + 1) & 1) * STAGE_STRIDE;
            #pragma unroll
            for (int u = 0; u < 16; ++u) {
                int idx = u * NTHREADS + t;
                int plane = idx >> 10;
                int off = (idx & 1023) * 16;
                cpa16(dstb + plane * PLANE_STRIDE + off,
                      g_scr + (size_t)plane * SCR_PLANE + tile_off + off);
            }
        }
        CPA_COMMIT();
        CPA_WAIT1();       // tile kt complete
        __syncthreads();

        // ---- phase 1: S = Q K^T (3-product bf16 split) ----
        float s[8][4];
        #pragma unroll
        for (int nt = 0; nt < 8; ++nt)
            #pragma unroll
            for (int c = 0; c < 4; ++c) s[nt][c] = 0.0f;

        #pragma unroll
        for (int kk = 0; kk < 8; ++kk) {
            #pragma unroll
            for (int ng = 0; ng < 4; ++ng) {
                uint32_t kh4[4], kl4[4];
                uint32_t off = swz(16 * ng + rB, bcB + kk * 32);
                ldsm4(kh4, stage + off);                      // KH plane
                ldsm4(kl4, stage + PLANE_STRIDE + off);       // KL plane
                mma16816(s[2 * ng],     qh[kk], kh4[0], kh4[1]);
                mma16816(s[2 * ng + 1], qh[kk], kh4[2], kh4[3]);
                mma16816(s[2 * ng],     ql[kk], kh4[0], kh4[1]);
                mma16816(s[2 * ng + 1], ql[kk], kh4[2], kh4[3]);
                mma16816(s[2 * ng],     qh[kk], kl4[0], kl4[1]);
                mma16816(s[2 * ng + 1], qh[kk], kl4[2], kl4[3]);
            }
        }

        // ---- mask (only affects last 2 tiles) ----
        if (s0 + TK - 1 > CP + e0) {
            const int j0 = s0 + 2 * (lane & 3);
            #pragma unroll
            for (int nt = 0; nt < 8; ++nt) {
                int jj = j0 + 8 * nt;
                if (jj     > lim0) s[nt][0] = NEG_INF;
                if (jj + 1 > lim0) s[nt][1] = NEG_INF;
                if (jj     > lim1) s[nt][2] = NEG_INF;
                if (jj + 1 > lim1) s[nt][3] = NEG_INF;
            }
        }

        // ---- online softmax ----
        float mt0 = NEG_INF, mt1 = NEG_INF;
        #pragma unroll
        for (int nt = 0; nt < 8; ++nt) {
            mt0 = fmaxf(mt0, fmaxf(s[nt][0], s[nt][1]));
            mt1 = fmaxf(mt1, fmaxf(s[nt][2], s[nt][3]));
        }
        mt0 = fmaxf(mt0, __shfl_xor_sync(0xffffffffu, mt0, 1));
        mt0 = fmaxf(mt0, __shfl_xor_sync(0xffffffffu, mt0, 2));
        mt1 = fmaxf(mt1, __shfl_xor_sync(0xffffffffu, mt1, 1));
        mt1 = fmaxf(mt1, __shfl_xor_sync(0xffffffffu, mt1, 2));

        float mn0 = fmaxf(m0, mt0), mn1 = fmaxf(m1, mt1);
        float sc0 = __expf(m0 - mn0), sc1 = __expf(m1 - mn1);
        m0 = mn0; m1 = mn1;

        float ps0 = 0.0f, ps1 = 0.0f;
        #pragma unroll
        for (int nt = 0; nt < 8; ++nt) {
            s[nt][0] = __expf(s[nt][0] - mn0);
            s[nt][1] = __expf(s[nt][1] - mn0);
            s[nt][2] = __expf(s[nt][2] - mn1);
            s[nt][3] = __expf(s[nt][3] - mn1);
            ps0 += s[nt][0] + s[nt][1];
            ps1 += s[nt][2] + s[nt][3];
        }
        ps0 += __shfl_xor_sync(0xffffffffu, ps0, 1);
        ps0 += __shfl_xor_sync(0xffffffffu, ps0, 2);
        ps1 += __shfl_xor_sync(0xffffffffu, ps1, 1);
        ps1 += __shfl_xor_sync(0xffffffffu, ps1, 2);
        l0 = l0 * sc0 + ps0;
        l1 = l1 * sc1 + ps1;

        #pragma unroll
        for (int j = 0; j < 16; ++j) {
            o[j][0] *= sc0; o[j][1] *= sc0;
            o[j][2] *= sc1; o[j][3] *= sc1;
        }

        // ---- phase 2: O += P V (3-product bf16 split) ----
        #pragma unroll
        for (int kk = 0; kk < 4; ++kk) {
            uint32_t ah[4], al[4];
            split2(s[2 * kk][0],     s[2 * kk][1],     ah[0], al[0]);
            split2(s[2 * kk][2],     s[2 * kk][3],     ah[1], al[1]);
            split2(s[2 * kk + 1][0], s[2 * kk + 1][1], ah[2], al[2]);
            split2(s[2 * kk + 1][2], s[2 * kk + 1][3], ah[3], al[3]);
            #pragma unroll
            for (int ng = 0; ng < 8; ++ng) {
                uint32_t vh4[4], vl4[4];
                uint32_t off = swz(16 * kk + rV, bcV + 32 * ng);
                ldsm4t(vh4, stage + 2 * PLANE_STRIDE + off);   // VH
                ldsm4t(vl4, stage + 3 * PLANE_STRIDE + off);   // VL
                mma16816(o[2 * ng],     ah, vh4[0], vh4[1]);
                mma16816(o[2 * ng + 1], ah, vh4[2], vh4[3]);
                mma16816(o[2 * ng],     al, vh4[0], vh4[1]);
                mma16816(o[2 * ng + 1], al, vh4[2], vh4[3]);
                mma16816(o[2 * ng],     ah, vl4[0], vl4[1]);
                mma16816(o[2 * ng + 1], ah, vl4[2], vl4[3]);
            }
        }
    }

    // ---- epilogue ----
    const float inv0 = 1.0f / l0, inv1 = 1.0f / l1;
    float* orow0 = out + (size_t)(b * CE + e0 + row0) * (CH * CD) + h * CD;
    float* orow1 = orow0 + (size_t)8 * (CH * CD);
    const int dc = 2 * (lane & 3);
    #pragma unroll
    for (int j = 0; j < 16; ++j) {
        float2 f0 = make_float2(o[j][0] * inv0, o[j][1] * inv0);
        float2 f1 = make_float2(o[j][2] * inv1, o[j][3] * inv1);
        *(float2*)(orow0 + 8 * j + dc) = f0;
        *(float2*)(orow1 + 8 * j + dc) = f1;
    }
}

extern "C" void kernel_launch(void* const* d_in, const int* in_sizes, int n_in,
                              void* d_out, int out_size) {
    (void)in_sizes; (void)n_in; (void)out_size;
    const float* q  = (const float*)d_in[0];
    const float* k  = (const float*)d_in[1];
    const float* v  = (const float*)d_in[2];
    const float* kc = (const float*)d_in[3];
    const float* vc = (const float*)d_in[4];
    float* out = (float*)d_out;

    prep_kv<<<(CB * CHK * CS * 16) / NTHREADS, NTHREADS>>>(k, v, kc, vc);

    cudaFuncSetAttribute(radix_extend_hmma,
                         cudaFuncAttributeMaxDynamicSharedMemorySize, SMEM_BYTES);
    dim3 grid(CE / TQ, CH, CB);   // (4, 32, 4) = 512 CTAs
    radix_extend_hmma<<<grid, NTHREADS, SMEM_BYTES>>>(q, out);
}

// round 7
// speedup vs baseline: 3.4632x; 1.0529x over previous
#include <cuda_runtime.h>
#include <cstdint>
#include <cstddef>

#define CB 4
#define CE 512
#define CP 1536
#define CH 32
#define CHK 8
#define CD 128
#define CS 2048
#define TQ 128
#define TK 64
#define NTHREADS 256
// SCALE * log2(e): scores computed directly in log2 domain
#define SCALE_L2E 0.12751741814489405f
#define NEG_INF -1e30f

// scratch: bf16 planes in swizzled layout, 256B per row
#define SCR_PLANE (16u * 1024 * 1024)
__device__ __align__(256) unsigned char g_scr[4ull * SCR_PLANE];  // KH,KL,VH,VL

// smem: Q planes + 2-stage K/V buffers
#define OFF_QH 0
#define OFF_QL 32768
#define OFF_ST 65536
#define STAGE_STRIDE 65536
#define PLANE_STRIDE 16384
#define SMEM_BYTES 196608

__device__ __forceinline__ uint32_t swz(uint32_t row, uint32_t byteCol) {
    return (row << 8) + (byteCol ^ ((row & 7) << 4));
}

__device__ __forceinline__ uint32_t smem_u32(const void* p) {
    uint32_t a;
    asm("{ .reg .u64 t; cvta.to.shared.u64 t, %1; cvt.u32.u64 %0, t; }"
        : "=r"(a) : "l"(p));
    return a;
}

__device__ __forceinline__ float ex2(float x) {
    float y;
    asm("ex2.approx.ftz.f32 %0, %1;" : "=f"(y) : "f"(x));
    return y;
}

// split pair of floats into bf16x2 hi (rn) + bf16x2 lo (residual)
__device__ __forceinline__ void split2(float x0, float x1,
                                       uint32_t& hp, uint32_t& lp) {
    asm("cvt.rn.bf16x2.f32 %0, %1, %2;" : "=r"(hp) : "f"(x1), "f"(x0));
    float h0 = __uint_as_float(hp << 16);
    float h1 = __uint_as_float(hp & 0xffff0000u);
    float l0 = x0 - h0;
    float l1 = x1 - h1;
    asm("cvt.rn.bf16x2.f32 %0, %1, %2;" : "=r"(lp) : "f"(l1), "f"(l0));
}

__device__ __forceinline__ void ldsm4(uint32_t r[4], uint32_t addr) {
    asm volatile("ldmatrix.sync.aligned.m8n8.x4.shared.b16 {%0,%1,%2,%3}, [%4];"
                 : "=r"(r[0]), "=r"(r[1]), "=r"(r[2]), "=r"(r[3]) : "r"(addr));
}
__device__ __forceinline__ void ldsm4t(uint32_t r[4], uint32_t addr) {
    asm volatile("ldmatrix.sync.aligned.m8n8.x4.trans.shared.b16 {%0,%1,%2,%3}, [%4];"
                 : "=r"(r[0]), "=r"(r[1]), "=r"(r[2]), "=r"(r[3]) : "r"(addr));
}

__device__ __forceinline__ void mma16816(float c[4], const uint32_t a[4],
                                         uint32_t b0, uint32_t b1) {
    asm volatile(
        "mma.sync.aligned.m16n8k16.row.col.f32.bf16.bf16.f32 "
        "{%0,%1,%2,%3}, {%4,%5,%6,%7}, {%8,%9}, {%0,%1,%2,%3};"
        : "+f"(c[0]), "+f"(c[1]), "+f"(c[2]), "+f"(c[3])
        : "r"(a[0]), "r"(a[1]), "r"(a[2]), "r"(a[3]), "r"(b0), "r"(b1));
}

__device__ __forceinline__ void cpa16(uint32_t dst, const void* src) {
    asm volatile("cp.async.cg.shared.global [%0], [%1], 16;"
                 :: "r"(dst), "l"(src) : "memory");
}
#define CPA_COMMIT() asm volatile("cp.async.commit_group;" ::: "memory")
#define CPA_WAIT1()  asm volatile("cp.async.wait_group 1;" ::: "memory")

// ---------------- prep kernel: fp32 K/V -> swizzled bf16 hi/lo planes ----------------
__global__ __launch_bounds__(NTHREADS)
void prep_kv(const float* __restrict__ gk,  const float* __restrict__ gv,
             const float* __restrict__ gkc, const float* __restrict__ gvc) {
    const int task = blockIdx.x * NTHREADS + threadIdx.x;
    const int g   = task & 15;
    const int s   = (task >> 4) & (CS - 1);
    const int khb = task >> 15;
    const int kh  = khb & 7, b = khb >> 3;

    const float *kr, *vr;
    if (s < CP) {
        size_t o = ((size_t)(b * CP + s) * CHK + kh) * CD;
        kr = gkc + o; vr = gvc + o;
    } else {
        size_t o = ((size_t)(b * CE + (s - CP)) * CHK + kh) * CD;
        kr = gk + o; vr = gv + o;
    }
    const int col = g * 8;
    const uint32_t dst = (((uint32_t)khb * CS + s) << 8) + ((g * 16) ^ ((s & 7) << 4));

    float4 x0, x1; uint4 hi, lo;
    x0 = *(const float4*)(kr + col); x1 = *(const float4*)(kr + col + 4);
    split2(x0.x, x0.y, hi.x, lo.x); split2(x0.z, x0.w, hi.y, lo.y);
    split2(x1.x, x1.y, hi.z, lo.z); split2(x1.z, x1.w, hi.w, lo.w);
    *(uint4*)(g_scr + 0ull * SCR_PLANE + dst) = hi;
    *(uint4*)(g_scr + 1ull * SCR_PLANE + dst) = lo;

    x0 = *(const float4*)(vr + col); x1 = *(const float4*)(vr + col + 4);
    split2(x0.x, x0.y, hi.x, lo.x); split2(x0.z, x0.w, hi.y, lo.y);
    split2(x1.x, x1.y, hi.z, lo.z); split2(x1.z, x1.w, hi.w, lo.w);
    *(uint4*)(g_scr + 2ull * SCR_PLANE + dst) = hi;
    *(uint4*)(g_scr + 3ull * SCR_PLANE + dst) = lo;
}

// ---------------- main attention kernel ----------------
__global__ __launch_bounds__(NTHREADS, 1)
void radix_extend_hmma(const float* __restrict__ gq, float* __restrict__ out) {
    extern __shared__ char smem[];
    const uint32_t sb = smem_u32(smem);
    const int t = threadIdx.x, w = t >> 5, lane = t & 31;
    const int e0 = blockIdx.x * TQ, h = blockIdx.y, b = blockIdx.z;
    const int khb = b * CHK + (h >> 2);
    const int ntiles = (CP + e0 + TQ) / TK;

    // prefetch tile 0 while we convert Q
    {
        const uint32_t tile_off = (((uint32_t)khb * CS) << 8);
        #pragma unroll
        for (int u = 0; u < 16; ++u) {
            int idx = u * NTHREADS + t;
            int plane = idx >> 10;
            int off = (idx & 1023) * 16;
            cpa16(sb + OFF_ST + plane * PLANE_STRIDE + off,
                  g_scr + (size_t)plane * SCR_PLANE + tile_off + off);
        }
    }
    CPA_COMMIT();

    // ---- load Q tile: fold scale*log2e, split bf16, swizzled store ----
    {
        const int qrow = t >> 1;
        const int cbase = (t & 1) * 64;
        const float* qr = gq + ((size_t)(b * CE + e0 + qrow) * CH + h) * CD;
        #pragma unroll
        for (int g = 0; g < 8; ++g) {
            int colf = cbase + 8 * g;
            float4 x0 = *(const float4*)(qr + colf);
            float4 x1 = *(const float4*)(qr + colf + 4);
            x0.x *= SCALE_L2E; x0.y *= SCALE_L2E; x0.z *= SCALE_L2E; x0.w *= SCALE_L2E;
            x1.x *= SCALE_L2E; x1.y *= SCALE_L2E; x1.z *= SCALE_L2E; x1.w *= SCALE_L2E;
            uint4 hi, lo;
            split2(x0.x, x0.y, hi.x, lo.x);
            split2(x0.z, x0.w, hi.y, lo.y);
            split2(x1.x, x1.y, hi.z, lo.z);
            split2(x1.z, x1.w, hi.w, lo.w);
            uint32_t off = swz(qrow, (uint32_t)colf * 2);
            *(uint4*)(smem + OFF_QH + off) = hi;
            *(uint4*)(smem + OFF_QL + off) = lo;
        }
    }
    __syncthreads();

    // ---- persistent Q-hi fragments; Q-lo reloaded per tile ----
    const uint32_t qrow = 16 * w + (lane & 7) + 8 * ((lane >> 3) & 1);
    const uint32_t qbc0 = 16 * (lane >> 4);
    uint32_t qh[8][4];
    #pragma unroll
    for (int kk = 0; kk < 8; ++kk)
        ldsm4(qh[kk], sb + OFF_QH + swz(qrow, qbc0 + kk * 32));

    const uint32_t rB  = (lane & 7) + 8 * (lane >> 4);
    const uint32_t bcB = 16 * ((lane >> 3) & 1);
    const uint32_t rV  = (lane & 7) + 8 * ((lane >> 3) & 1);
    const uint32_t bcV = 16 * (lane >> 4);

    const int row0 = 16 * w + (lane >> 2);
    const int lim0 = CP + e0 + row0;
    const int lim1 = lim0 + 8;
    float m0 = NEG_INF, m1 = NEG_INF, l0 = 0.0f, l1 = 0.0f;

    float o[16][4];
    #pragma unroll
    for (int j = 0; j < 16; ++j)
        #pragma unroll
        for (int c = 0; c < 4; ++c) o[j][c] = 0.0f;

    for (int kt = 0; kt < ntiles; ++kt) {
        const int s0 = kt * TK;
        const uint32_t stage = sb + OFF_ST + (kt & 1) * STAGE_STRIDE;

        __syncthreads();

        if (kt + 1 < ntiles) {
            const uint32_t tile_off = (((uint32_t)khb * CS + (s0 + TK)) << 8);
            const uint32_t dstb = sb + OFF_ST + ((kt + 1) & 1) * STAGE_STRIDE;
            #pragma unroll
            for (int u = 0; u < 16; ++u) {
                int idx = u * NTHREADS + t;
                int plane = idx >> 10;
                int off = (idx & 1023) * 16;
                cpa16(dstb + plane * PLANE_STRIDE + off,
                      g_scr + (size_t)plane * SCR_PLANE + tile_off + off);
            }
        }
        CPA_COMMIT();
        CPA_WAIT1();
        __syncthreads();

        // ---- phase 1: S = Q K^T, double-buffered fragments ----
        float s[8][4];
        #pragma unroll
        for (int nt = 0; nt < 8; ++nt)
            #pragma unroll
            for (int c = 0; c < 4; ++c) s[nt][c] = 0.0f;

        uint32_t kfh[2][4], kfl[2][4], qlv[2][4];
        ldsm4(kfh[0], stage + swz(rB, bcB));
        ldsm4(kfl[0], stage + PLANE_STRIDE + swz(rB, bcB));
        ldsm4(qlv[0], sb + OFF_QL + swz(qrow, qbc0));

        #pragma unroll
        for (int it = 0; it < 32; ++it) {
            const int kk = it >> 2, ng = it & 3;
            const int cur = it & 1, nxt = cur ^ 1;
            if (it + 1 < 32) {
                const int kk2 = (it + 1) >> 2, ng2 = (it + 1) & 3;
                uint32_t off = swz(16 * ng2 + rB, bcB + kk2 * 32);
                ldsm4(kfh[nxt], stage + off);
                ldsm4(kfl[nxt], stage + PLANE_STRIDE + off);
                if (ng == 3)   // entering new kk next iter: prefetch its Q-lo
                    ldsm4(qlv[(kk + 1) & 1], sb + OFF_QL + swz(qrow, qbc0 + kk2 * 32));
            }
            const int qc = kk & 1;
            mma16816(s[2 * ng],     qh[kk],  kfh[cur][0], kfh[cur][1]);
            mma16816(s[2 * ng + 1], qh[kk],  kfh[cur][2], kfh[cur][3]);
            mma16816(s[2 * ng],     qlv[qc], kfh[cur][0], kfh[cur][1]);
            mma16816(s[2 * ng + 1], qlv[qc], kfh[cur][2], kfh[cur][3]);
            mma16816(s[2 * ng],     qh[kk],  kfl[cur][0], kfl[cur][1]);
            mma16816(s[2 * ng + 1], qh[kk],  kfl[cur][2], kfl[cur][3]);
        }

        // ---- mask (only last 2 tiles) ----
        if (s0 + TK - 1 > CP + e0) {
            const int j0 = s0 + 2 * (lane & 3);
            #pragma unroll
            for (int nt = 0; nt < 8; ++nt) {
                int jj = j0 + 8 * nt;
                if (jj     > lim0) s[nt][0] = NEG_INF;
                if (jj + 1 > lim0) s[nt][1] = NEG_INF;
                if (jj     > lim1) s[nt][2] = NEG_INF;
                if (jj + 1 > lim1) s[nt][3] = NEG_INF;
            }
        }

        // ---- online softmax (log2 domain) ----
        float mt0 = NEG_INF, mt1 = NEG_INF;
        #pragma unroll
        for (int nt = 0; nt < 8; ++nt) {
            mt0 = fmaxf(mt0, fmaxf(s[nt][0], s[nt][1]));
            mt1 = fmaxf(mt1, fmaxf(s[nt][2], s[nt][3]));
        }
        mt0 = fmaxf(mt0, __shfl_xor_sync(0xffffffffu, mt0, 1));
        mt0 = fmaxf(mt0, __shfl_xor_sync(0xffffffffu, mt0, 2));
        mt1 = fmaxf(mt1, __shfl_xor_sync(0xffffffffu, mt1, 1));
        mt1 = fmaxf(mt1, __shfl_xor_sync(0xffffffffu, mt1, 2));

        float mn0 = fmaxf(m0, mt0), mn1 = fmaxf(m1, mt1);
        float sc0 = ex2(m0 - mn0), sc1 = ex2(m1 - mn1);
        m0 = mn0; m1 = mn1;

        float ps0 = 0.0f, ps1 = 0.0f;
        #pragma unroll
        for (int nt = 0; nt < 8; ++nt) {
            s[nt][0] = ex2(s[nt][0] - mn0);
            s[nt][1] = ex2(s[nt][1] - mn0);
            s[nt][2] = ex2(s[nt][2] - mn1);
            s[nt][3] = ex2(s[nt][3] - mn1);
            ps0 += s[nt][0] + s[nt][1];
            ps1 += s[nt][2] + s[nt][3];
        }
        ps0 += __shfl_xor_sync(0xffffffffu, ps0, 1);
        ps0 += __shfl_xor_sync(0xffffffffu, ps0, 2);
        ps1 += __shfl_xor_sync(0xffffffffu, ps1, 1);
        ps1 += __shfl_xor_sync(0xffffffffu, ps1, 2);
        l0 = l0 * sc0 + ps0;
        l1 = l1 * sc1 + ps1;

        #pragma unroll
        for (int j = 0; j < 16; ++j) {
            o[j][0] *= sc0; o[j][1] *= sc0;
            o[j][2] *= sc1; o[j][3] *= sc1;
        }

        // ---- phase 2: O += P V, double-buffered fragments ----
        uint32_t vfh[2][4], vfl[2][4];
        ldsm4t(vfh[0], stage + 2 * PLANE_STRIDE + swz(rV, bcV));
        ldsm4t(vfl[0], stage + 3 * PLANE_STRIDE + swz(rV, bcV));

        uint32_t ah[4], al[4];
        split2(s[0][0], s[0][1], ah[0], al[0]);
        split2(s[0][2], s[0][3], ah[1], al[1]);
        split2(s[1][0], s[1][1], ah[2], al[2]);
        split2(s[1][2], s[1][3], ah[3], al[3]);

        #pragma unroll
        for (int it = 0; it < 32; ++it) {
            const int kk = it >> 3, ng = it & 7;
            const int cur = it & 1, nxt = cur ^ 1;
            if (it + 1 < 32) {
                const int kk2 = (it + 1) >> 3, ng2 = (it + 1) & 7;
                uint32_t off = swz(16 * kk2 + rV, bcV + 32 * ng2);
                ldsm4t(vfh[nxt], stage + 2 * PLANE_STRIDE + off);
                ldsm4t(vfl[nxt], stage + 3 * PLANE_STRIDE + off);
            }
            mma16816(o[2 * ng],     ah, vfh[cur][0], vfh[cur][1]);
            mma16816(o[2 * ng + 1], ah, vfh[cur][2], vfh[cur][3]);
            mma16816(o[2 * ng],     al, vfh[cur][0], vfh[cur][1]);
            mma16816(o[2 * ng + 1], al, vfh[cur][2], vfh[cur][3]);
            mma16816(o[2 * ng],     ah, vfl[cur][0], vfl[cur][1]);
            mma16816(o[2 * ng + 1], ah, vfl[cur][2], vfl[cur][3]);
            if (ng == 7 && kk < 3) {   // next kk: refresh P fragments
                split2(s[2 * kk + 2][0], s[2 * kk + 2][1], ah[0], al[0]);
                split2(s[2 * kk + 2][2], s[2 * kk + 2][3], ah[1], al[1]);
                split2(s[2 * kk + 3][0], s[2 * kk + 3][1], ah[2], al[2]);
                split2(s[2 * kk + 3][2], s[2 * kk + 3][3], ah[3], al[3]);
            }
        }
    }

    // ---- epilogue ----
    const float inv0 = 1.0f / l0, inv1 = 1.0f / l1;
    float* orow0 = out + (size_t)(b * CE + e0 + row0) * (CH * CD) + h * CD;
    float* orow1 = orow0 + (size_t)8 * (CH * CD);
    const int dc = 2 * (lane & 3);
    #pragma unroll
    for (int j = 0; j < 16; ++j) {
        float2 f0 = make_float2(o[j][0] * inv0, o[j][1] * inv0);
        float2 f1 = make_float2(o[j][2] * inv1, o[j][3] * inv1);
        *(float2*)(orow0 + 8 * j + dc) = f0;
        *(float2*)(orow1 + 8 * j + dc) = f1;
    }
}

extern "C" void kernel_launch(void* const* d_in, const int* in_sizes, int n_in,
                              void* d_out, int out_size) {
    (void)in_sizes; (void)n_in; (void)out_size;
    const float* q  = (const float*)d_in[0];
    const float* k  = (const float*)d_in[1];
    const float* v  = (const float*)d_in[2];
    const float* kc = (const float*)d_in[3];
    const float* vc = (const float*)d_in[4];
    float* out = (float*)d_out;

    prep_kv<<<(CB * CHK * CS * 16) / NTHREADS, NTHREADS>>>(k, v, kc, vc);

    cudaFuncSetAttribute(radix_extend_hmma,
                         cudaFuncAttributeMaxDynamicSharedMemorySize, SMEM_BYTES);
    dim3 grid(CE / TQ, CH, CB);   // (4, 32, 4) = 512 CTAs
    radix_extend_hmma<<<grid, NTHREADS, SMEM_BYTES>>>(q, out);
}

// round 8
// speedup vs baseline: 4.9700x; 1.4351x over previous
#include <cuda_runtime.h>
#include <cstdint>
#include <cstddef>

#define CB 4
#define CE 512
#define CP 1536
#define CH 32
#define CHK 8
#define CD 128
#define CS 2048
#define TQ 128
#define TK 64
#define NTHREADS 256
// SCALE * log2(e): scores computed directly in log2 domain
#define SCALE_L2E 0.12751741814489405f
#define NEG_INF -1e30f

// scratch: fp16 K and V planes in swizzled layout, 256B per row
#define SCR_PLANE (16u * 1024 * 1024)
__device__ __align__(256) unsigned char g_scr[2ull * SCR_PLANE];  // K, V

// smem: Q hi/lo planes + 2-stage K/V buffers
#define OFF_QH 0
#define OFF_QL 32768
#define OFF_ST 65536
#define STAGE_STRIDE 32768
#define PLANE_STRIDE 16384
#define SMEM_BYTES 131072

__device__ __forceinline__ uint32_t swz(uint32_t row, uint32_t byteCol) {
    return (row << 8) + (byteCol ^ ((row & 7) << 4));
}

__device__ __forceinline__ uint32_t smem_u32(const void* p) {
    uint32_t a;
    asm("{ .reg .u64 t; cvta.to.shared.u64 t, %1; cvt.u32.u64 %0, t; }"
        : "=r"(a) : "l"(p));
    return a;
}

__device__ __forceinline__ float ex2(float x) {
    float y;
    asm("ex2.approx.ftz.f32 %0, %1;" : "=f"(y) : "f"(x));
    return y;
}

// pack two floats to f16x2 (rn)
__device__ __forceinline__ uint32_t packh(float x0, float x1) {
    uint32_t r;
    asm("cvt.rn.f16x2.f32 %0, %1, %2;" : "=r"(r) : "f"(x1), "f"(x0));
    return r;
}

// split pair of floats into f16x2 hi (rn) + f16x2 lo (residual)
__device__ __forceinline__ void split2h(float x0, float x1,
                                        uint32_t& hp, uint32_t& lp) {
    asm("cvt.rn.f16x2.f32 %0, %1, %2;" : "=r"(hp) : "f"(x1), "f"(x0));
    float h0, h1;
    asm("{ .reg .b16 a, b;\n\t"
        "mov.b32 {a, b}, %2;\n\t"
        "cvt.f32.f16 %0, a;\n\t"
        "cvt.f32.f16 %1, b; }"
        : "=f"(h0), "=f"(h1) : "r"(hp));
    float l0 = x0 - h0, l1 = x1 - h1;
    asm("cvt.rn.f16x2.f32 %0, %1, %2;" : "=r"(lp) : "f"(l1), "f"(l0));
}

__device__ __forceinline__ void ldsm4(uint32_t r[4], uint32_t addr) {
    asm volatile("ldmatrix.sync.aligned.m8n8.x4.shared.b16 {%0,%1,%2,%3}, [%4];"
                 : "=r"(r[0]), "=r"(r[1]), "=r"(r[2]), "=r"(r[3]) : "r"(addr));
}
__device__ __forceinline__ void ldsm4t(uint32_t r[4], uint32_t addr) {
    asm volatile("ldmatrix.sync.aligned.m8n8.x4.trans.shared.b16 {%0,%1,%2,%3}, [%4];"
                 : "=r"(r[0]), "=r"(r[1]), "=r"(r[2]), "=r"(r[3]) : "r"(addr));
}

__device__ __forceinline__ void mma16816h(float c[4], const uint32_t a[4],
                                          uint32_t b0, uint32_t b1) {
    asm volatile(
        "mma.sync.aligned.m16n8k16.row.col.f32.f16.f16.f32 "
        "{%0,%1,%2,%3}, {%4,%5,%6,%7}, {%8,%9}, {%0,%1,%2,%3};"
        : "+f"(c[0]), "+f"(c[1]), "+f"(c[2]), "+f"(c[3])
        : "r"(a[0]), "r"(a[1]), "r"(a[2]), "r"(a[3]), "r"(b0), "r"(b1));
}

__device__ __forceinline__ void cpa16(uint32_t dst, const void* src) {
    asm volatile("cp.async.cg.shared.global [%0], [%1], 16;"
                 :: "r"(dst), "l"(src) : "memory");
}
#define CPA_COMMIT() asm volatile("cp.async.commit_group;" ::: "memory")
#define CPA_WAIT1()  asm volatile("cp.async.wait_group 1;" ::: "memory")

// ---------------- prep kernel: fp32 K/V -> swizzled fp16 planes ----------------
__global__ __launch_bounds__(NTHREADS)
void prep_kv(const float* __restrict__ gk,  const float* __restrict__ gv,
             const float* __restrict__ gkc, const float* __restrict__ gvc) {
    const int task = blockIdx.x * NTHREADS + threadIdx.x;
    const int g   = task & 15;
    const int s   = (task >> 4) & (CS - 1);
    const int khb = task >> 15;
    const int kh  = khb & 7, b = khb >> 3;

    const float *kr, *vr;
    if (s < CP) {
        size_t o = ((size_t)(b * CP + s) * CHK + kh) * CD;
        kr = gkc + o; vr = gvc + o;
    } else {
        size_t o = ((size_t)(b * CE + (s - CP)) * CHK + kh) * CD;
        kr = gk + o; vr = gv + o;
    }
    const int col = g * 8;
    const uint32_t dst = (((uint32_t)khb * CS + s) << 8) + ((g * 16) ^ ((s & 7) << 4));

    float4 x0 = *(const float4*)(kr + col);
    float4 x1 = *(const float4*)(kr + col + 4);
    uint4 p;
    p.x = packh(x0.x, x0.y); p.y = packh(x0.z, x0.w);
    p.z = packh(x1.x, x1.y); p.w = packh(x1.z, x1.w);
    *(uint4*)(g_scr + 0ull * SCR_PLANE + dst) = p;

    x0 = *(const float4*)(vr + col);
    x1 = *(const float4*)(vr + col + 4);
    p.x = packh(x0.x, x0.y); p.y = packh(x0.z, x0.w);
    p.z = packh(x1.x, x1.y); p.w = packh(x1.z, x1.w);
    *(uint4*)(g_scr + 1ull * SCR_PLANE + dst) = p;
}

// ---------------- main attention kernel ----------------
__global__ __launch_bounds__(NTHREADS, 1)
void radix_extend_hmma(const float* __restrict__ gq, float* __restrict__ out) {
    extern __shared__ char smem[];
    const uint32_t sb = smem_u32(smem);
    const int t = threadIdx.x, w = t >> 5, lane = t & 31;
    const int e0 = blockIdx.x * TQ, h = blockIdx.y, b = blockIdx.z;
    const int khb = b * CHK + (h >> 2);
    const int ntiles = (CP + e0 + TQ) / TK;

    // prefetch tile 0 (K+V planes, 32KB) while we convert Q
    {
        const uint32_t tile_off = (((uint32_t)khb * CS) << 8);
        #pragma unroll
        for (int u = 0; u < 8; ++u) {
            int idx = u * NTHREADS + t;          // 0..2047
            int plane = idx >> 10;
            int off = (idx & 1023) * 16;
            cpa16(sb + OFF_ST + plane * PLANE_STRIDE + off,
                  g_scr + (size_t)plane * SCR_PLANE + tile_off + off);
        }
    }
    CPA_COMMIT();

    // ---- load Q tile: fold scale*log2e, split fp16 hi/lo, swizzled store ----
    {
        const int qrow = t >> 1;
        const int cbase = (t & 1) * 64;
        const float* qr = gq + ((size_t)(b * CE + e0 + qrow) * CH + h) * CD;
        #pragma unroll
        for (int g = 0; g < 8; ++g) {
            int colf = cbase + 8 * g;
            float4 x0 = *(const float4*)(qr + colf);
            float4 x1 = *(const float4*)(qr + colf + 4);
            x0.x *= SCALE_L2E; x0.y *= SCALE_L2E; x0.z *= SCALE_L2E; x0.w *= SCALE_L2E;
            x1.x *= SCALE_L2E; x1.y *= SCALE_L2E; x1.z *= SCALE_L2E; x1.w *= SCALE_L2E;
            uint4 hi, lo;
            split2h(x0.x, x0.y, hi.x, lo.x);
            split2h(x0.z, x0.w, hi.y, lo.y);
            split2h(x1.x, x1.y, hi.z, lo.z);
            split2h(x1.z, x1.w, hi.w, lo.w);
            uint32_t off = swz(qrow, (uint32_t)colf * 2);
            *(uint4*)(smem + OFF_QH + off) = hi;
            *(uint4*)(smem + OFF_QL + off) = lo;
        }
    }
    __syncthreads();

    // ---- persistent Q hi/lo fragments ----
    const uint32_t qrow = 16 * w + (lane & 7) + 8 * ((lane >> 3) & 1);
    const uint32_t qbc0 = 16 * (lane >> 4);
    uint32_t qh[8][4], ql[8][4];
    #pragma unroll
    for (int kk = 0; kk < 8; ++kk) {
        ldsm4(qh[kk], sb + OFF_QH + swz(qrow, qbc0 + kk * 32));
        ldsm4(ql[kk], sb + OFF_QL + swz(qrow, qbc0 + kk * 32));
    }

    const uint32_t rB  = (lane & 7) + 8 * (lane >> 4);
    const uint32_t bcB = 16 * ((lane >> 3) & 1);
    const uint32_t rV  = (lane & 7) + 8 * ((lane >> 3) & 1);
    const uint32_t bcV = 16 * (lane >> 4);

    const int row0 = 16 * w + (lane >> 2);
    const int lim0 = CP + e0 + row0;
    const int lim1 = lim0 + 8;
    float m0 = NEG_INF, m1 = NEG_INF, l0 = 0.0f, l1 = 0.0f;

    float o[16][4];
    #pragma unroll
    for (int j = 0; j < 16; ++j)
        #pragma unroll
        for (int c = 0; c < 4; ++c) o[j][c] = 0.0f;

    for (int kt = 0; kt < ntiles; ++kt) {
        const int s0 = kt * TK;
        const uint32_t stage = sb + OFF_ST + (kt & 1) * STAGE_STRIDE;

        __syncthreads();

        if (kt + 1 < ntiles) {
            const uint32_t tile_off = (((uint32_t)khb * CS + (s0 + TK)) << 8);
            const uint32_t dstb = sb + OFF_ST + ((kt + 1) & 1) * STAGE_STRIDE;
            #pragma unroll
            for (int u = 0; u < 8; ++u) {
                int idx = u * NTHREADS + t;
                int plane = idx >> 10;
                int off = (idx & 1023) * 16;
                cpa16(dstb + plane * PLANE_STRIDE + off,
                      g_scr + (size_t)plane * SCR_PLANE + tile_off + off);
            }
        }
        CPA_COMMIT();
        CPA_WAIT1();
        __syncthreads();

        // ---- phase 1: S = (Qh + Ql) Kh^T, double-buffered K fragments ----
        float s[8][4];
        #pragma unroll
        for (int nt = 0; nt < 8; ++nt)
            #pragma unroll
            for (int c = 0; c < 4; ++c) s[nt][c] = 0.0f;

        uint32_t kf[2][4];
        ldsm4(kf[0], stage + swz(rB, bcB));

        #pragma unroll
        for (int it = 0; it < 32; ++it) {
            const int kk = it >> 2, ng = it & 3;
            const int cur = it & 1, nxt = cur ^ 1;
            if (it + 1 < 32) {
                const int kk2 = (it + 1) >> 2, ng2 = (it + 1) & 3;
                ldsm4(kf[nxt], stage + swz(16 * ng2 + rB, bcB + kk2 * 32));
            }
            mma16816h(s[2 * ng],     qh[kk], kf[cur][0], kf[cur][1]);
            mma16816h(s[2 * ng + 1], qh[kk], kf[cur][2], kf[cur][3]);
            mma16816h(s[2 * ng],     ql[kk], kf[cur][0], kf[cur][1]);
            mma16816h(s[2 * ng + 1], ql[kk], kf[cur][2], kf[cur][3]);
        }

        // ---- mask (only last 2 tiles) ----
        if (s0 + TK - 1 > CP + e0) {
            const int j0 = s0 + 2 * (lane & 3);
            #pragma unroll
            for (int nt = 0; nt < 8; ++nt) {
                int jj = j0 + 8 * nt;
                if (jj     > lim0) s[nt][0] = NEG_INF;
                if (jj + 1 > lim0) s[nt][1] = NEG_INF;
                if (jj     > lim1) s[nt][2] = NEG_INF;
                if (jj + 1 > lim1) s[nt][3] = NEG_INF;
            }
        }

        // ---- online softmax (log2 domain) ----
        float mt0 = NEG_INF, mt1 = NEG_INF;
        #pragma unroll
        for (int nt = 0; nt < 8; ++nt) {
            mt0 = fmaxf(mt0, fmaxf(s[nt][0], s[nt][1]));
            mt1 = fmaxf(mt1, fmaxf(s[nt][2], s[nt][3]));
        }
        mt0 = fmaxf(mt0, __shfl_xor_sync(0xffffffffu, mt0, 1));
        mt0 = fmaxf(mt0, __shfl_xor_sync(0xffffffffu, mt0, 2));
        mt1 = fmaxf(mt1, __shfl_xor_sync(0xffffffffu, mt1, 1));
        mt1 = fmaxf(mt1, __shfl_xor_sync(0xffffffffu, mt1, 2));

        float mn0 = fmaxf(m0, mt0), mn1 = fmaxf(m1, mt1);
        float sc0 = ex2(m0 - mn0), sc1 = ex2(m1 - mn1);
        m0 = mn0; m1 = mn1;

        float ps0 = 0.0f, ps1 = 0.0f;
        #pragma unroll
        for (int nt = 0; nt < 8; ++nt) {
            s[nt][0] = ex2(s[nt][0] - mn0);
            s[nt][1] = ex2(s[nt][1] - mn0);
            s[nt][2] = ex2(s[nt][2] - mn1);
            s[nt][3] = ex2(s[nt][3] - mn1);
            ps0 += s[nt][0] + s[nt][1];
            ps1 += s[nt][2] + s[nt][3];
        }
        ps0 += __shfl_xor_sync(0xffffffffu, ps0, 1);
        ps0 += __shfl_xor_sync(0xffffffffu, ps0, 2);
        ps1 += __shfl_xor_sync(0xffffffffu, ps1, 1);
        ps1 += __shfl_xor_sync(0xffffffffu, ps1, 2);
        l0 = l0 * sc0 + ps0;
        l1 = l1 * sc1 + ps1;

        #pragma unroll
        for (int j = 0; j < 16; ++j) {
            o[j][0] *= sc0; o[j][1] *= sc0;
            o[j][2] *= sc1; o[j][3] *= sc1;
        }

        // ---- phase 2: O += (Ph + Pl) Vh, double-buffered V fragments ----
        uint32_t vf[2][4];
        ldsm4t(vf[0], stage + PLANE_STRIDE + swz(rV, bcV));

        uint32_t ah[4], al[4];
        split2h(s[0][0], s[0][1], ah[0], al[0]);
        split2h(s[0][2], s[0][3], ah[1], al[1]);
        split2h(s[1][0], s[1][1], ah[2], al[2]);
        split2h(s[1][2], s[1][3], ah[3], al[3]);

        #pragma unroll
        for (int it = 0; it < 32; ++it) {
            const int kk = it >> 3, ng = it & 7;
            const int cur = it & 1, nxt = cur ^ 1;
            if (it + 1 < 32) {
                const int kk2 = (it + 1) >> 3, ng2 = (it + 1) & 7;
                ldsm4t(vf[nxt], stage + PLANE_STRIDE + swz(16 * kk2 + rV, bcV + 32 * ng2));
            }
            mma16816h(o[2 * ng],     ah, vf[cur][0], vf[cur][1]);
            mma16816h(o[2 * ng + 1], ah, vf[cur][2], vf[cur][3]);
            mma16816h(o[2 * ng],     al, vf[cur][0], vf[cur][1]);
            mma16816h(o[2 * ng + 1], al, vf[cur][2], vf[cur][3]);
            if (ng == 7 && kk < 3) {
                split2h(s[2 * kk + 2][0], s[2 * kk + 2][1], ah[0], al[0]);
                split2h(s[2 * kk + 2][2], s[2 * kk + 2][3], ah[1], al[1]);
                split2h(s[2 * kk + 3][0], s[2 * kk + 3][1], ah[2], al[2]);
                split2h(s[2 * kk + 3][2], s[2 * kk + 3][3], ah[3], al[3]);
            }
        }
    }

    // ---- epilogue ----
    const float inv0 = 1.0f / l0, inv1 = 1.0f / l1;
    float* orow0 = out + (size_t)(b * CE + e0 + row0) * (CH * CD) + h * CD;
    float* orow1 = orow0 + (size_t)8 * (CH * CD);
    const int dc = 2 * (lane & 3);
    #pragma unroll
    for (int j = 0; j < 16; ++j) {
        float2 f0 = make_float2(o[j][0] * inv0, o[j][1] * inv0);
        float2 f1 = make_float2(o[j][2] * inv1, o[j][3] * inv1);
        *(float2*)(orow0 + 8 * j + dc) = f0;
        *(float2*)(orow1 + 8 * j + dc) = f1;
    }
}

extern "C" void kernel_launch(void* const* d_in, const int* in_sizes, int n_in,
                              void* d_out, int out_size) {
    (void)in_sizes; (void)n_in; (void)out_size;
    const float* q  = (const float*)d_in[0];
    const float* k  = (const float*)d_in[1];
    const float* v  = (const float*)d_in[2];
    const float* kc = (const float*)d_in[3];
    const float* vc = (const float*)d_in[4];
    float* out = (float*)d_out;

    prep_kv<<<(CB * CHK * CS * 16) / NTHREADS, NTHREADS>>>(k, v, kc, vc);

    cudaFuncSetAttribute(radix_extend_hmma,
                         cudaFuncAttributeMaxDynamicSharedMemorySize, SMEM_BYTES);
    dim3 grid(CE / TQ, CH, CB);   // (4, 32, 4) = 512 CTAs
    radix_extend_hmma<<<grid, NTHREADS, SMEM_BYTES>>>(q, out);
}

// round 9
// speedup vs baseline: 5.6734x; 1.1415x over previous
#include <cuda_runtime.h>
#include <cstdint>
#include <cstddef>

#define CB 4
#define CE 512
#define CP 1536
#define CH 32
#define CHK 8
#define CD 128
#define CS 2048
#define TQ 64
#define TK 64
#define NTHREADS 128
// SCALE * log2(e): scores computed directly in log2 domain
#define SCALE_L2E 0.12751741814489405f
#define NEG_INF -1e30f

// scratch: fp16 K and V planes in swizzled layout, 256B per row
#define SCR_PLANE (16u * 1024 * 1024)
__device__ __align__(256) unsigned char g_scr[2ull * SCR_PLANE];  // K, V

// smem: Q hi/lo planes (16KB each) + 2-stage K/V buffers (32KB each)
#define OFF_QH 0
#define OFF_QL 16384
#define OFF_ST 32768
#define STAGE_STRIDE 32768
#define PLANE_STRIDE 16384
#define SMEM_BYTES 98304

__device__ __forceinline__ uint32_t swz(uint32_t row, uint32_t byteCol) {
    return (row << 8) + (byteCol ^ ((row & 7) << 4));
}

__device__ __forceinline__ uint32_t smem_u32(const void* p) {
    uint32_t a;
    asm("{ .reg .u64 t; cvta.to.shared.u64 t, %1; cvt.u32.u64 %0, t; }"
        : "=r"(a) : "l"(p));
    return a;
}

__device__ __forceinline__ float ex2(float x) {
    float y;
    asm("ex2.approx.ftz.f32 %0, %1;" : "=f"(y) : "f"(x));
    return y;
}

// pack two floats to f16x2 (rn)
__device__ __forceinline__ uint32_t packh(float x0, float x1) {
    uint32_t r;
    asm("cvt.rn.f16x2.f32 %0, %1, %2;" : "=r"(r) : "f"(x1), "f"(x0));
    return r;
}

// split pair of floats into f16x2 hi (rn) + f16x2 lo (residual)
__device__ __forceinline__ void split2h(float x0, float x1,
                                        uint32_t& hp, uint32_t& lp) {
    asm("cvt.rn.f16x2.f32 %0, %1, %2;" : "=r"(hp) : "f"(x1), "f"(x0));
    float h0, h1;
    asm("{ .reg .b16 a, b;\n\t"
        "mov.b32 {a, b}, %2;\n\t"
        "cvt.f32.f16 %0, a;\n\t"
        "cvt.f32.f16 %1, b; }"
        : "=f"(h0), "=f"(h1) : "r"(hp));
    float l0 = x0 - h0, l1 = x1 - h1;
    asm("cvt.rn.f16x2.f32 %0, %1, %2;" : "=r"(lp) : "f"(l1), "f"(l0));
}

__device__ __forceinline__ void ldsm4(uint32_t r[4], uint32_t addr) {
    asm volatile("ldmatrix.sync.aligned.m8n8.x4.shared.b16 {%0,%1,%2,%3}, [%4];"
                 : "=r"(r[0]), "=r"(r[1]), "=r"(r[2]), "=r"(r[3]) : "r"(addr));
}
__device__ __forceinline__ void ldsm4t(uint32_t r[4], uint32_t addr) {
    asm volatile("ldmatrix.sync.aligned.m8n8.x4.trans.shared.b16 {%0,%1,%2,%3}, [%4];"
                 : "=r"(r[0]), "=r"(r[1]), "=r"(r[2]), "=r"(r[3]) : "r"(addr));
}

__device__ __forceinline__ void mma16816h(float c[4], const uint32_t a[4],
                                          uint32_t b0, uint32_t b1) {
    asm volatile(
        "mma.sync.aligned.m16n8k16.row.col.f32.f16.f16.f32 "
        "{%0,%1,%2,%3}, {%4,%5,%6,%7}, {%8,%9}, {%0,%1,%2,%3};"
        : "+f"(c[0]), "+f"(c[1]), "+f"(c[2]), "+f"(c[3])
        : "r"(a[0]), "r"(a[1]), "r"(a[2]), "r"(a[3]), "r"(b0), "r"(b1));
}

__device__ __forceinline__ void cpa16(uint32_t dst, const void* src) {
    asm volatile("cp.async.cg.shared.global [%0], [%1], 16;"
                 :: "r"(dst), "l"(src) : "memory");
}
#define CPA_COMMIT() asm volatile("cp.async.commit_group;" ::: "memory")
#define CPA_WAIT1()  asm volatile("cp.async.wait_group 1;" ::: "memory")

// ---------------- prep kernel: fp32 K/V -> swizzled fp16 planes ----------------
__global__ __launch_bounds__(256)
void prep_kv(const float* __restrict__ gk,  const float* __restrict__ gv,
             const float* __restrict__ gkc, const float* __restrict__ gvc) {
    const int task = blockIdx.x * 256 + threadIdx.x;
    const int g   = task & 15;
    const int s   = (task >> 4) & (CS - 1);
    const int khb = task >> 15;
    const int kh  = khb & 7, b = khb >> 3;

    const float *kr, *vr;
    if (s < CP) {
        size_t o = ((size_t)(b * CP + s) * CHK + kh) * CD;
        kr = gkc + o; vr = gvc + o;
    } else {
        size_t o = ((size_t)(b * CE + (s - CP)) * CHK + kh) * CD;
        kr = gk + o; vr = gv + o;
    }
    const int col = g * 8;
    const uint32_t dst = (((uint32_t)khb * CS + s) << 8) + ((g * 16) ^ ((s & 7) << 4));

    float4 x0 = *(const float4*)(kr + col);
    float4 x1 = *(const float4*)(kr + col + 4);
    uint4 p;
    p.x = packh(x0.x, x0.y); p.y = packh(x0.z, x0.w);
    p.z = packh(x1.x, x1.y); p.w = packh(x1.z, x1.w);
    *(uint4*)(g_scr + 0ull * SCR_PLANE + dst) = p;

    x0 = *(const float4*)(vr + col);
    x1 = *(const float4*)(vr + col + 4);
    p.x = packh(x0.x, x0.y); p.y = packh(x0.z, x0.w);
    p.z = packh(x1.x, x1.y); p.w = packh(x1.z, x1.w);
    *(uint4*)(g_scr + 1ull * SCR_PLANE + dst) = p;
}

// ---------------- main attention kernel (2 CTAs/SM) ----------------
__global__ __launch_bounds__(NTHREADS, 2)
void radix_extend_hmma(const float* __restrict__ gq, float* __restrict__ out) {
    extern __shared__ char smem[];
    const uint32_t sb = smem_u32(smem);
    const int t = threadIdx.x, w = t >> 5, lane = t & 31;
    const int e0 = blockIdx.x * TQ, h = blockIdx.y, b = blockIdx.z;
    const int khb = b * CHK + (h >> 2);
    const int ntiles = (CP + e0 + TQ) / TK;

    // prefetch tile 0 (K+V planes, 32KB) while we convert Q
    {
        const uint32_t tile_off = (((uint32_t)khb * CS) << 8);
        #pragma unroll
        for (int u = 0; u < 16; ++u) {
            int idx = u * NTHREADS + t;          // 0..2047
            int plane = idx >> 10;
            int off = (idx & 1023) * 16;
            cpa16(sb + OFF_ST + plane * PLANE_STRIDE + off,
                  g_scr + (size_t)plane * SCR_PLANE + tile_off + off);
        }
    }
    CPA_COMMIT();

    // ---- load Q tile: fold scale*log2e, split fp16 hi/lo, swizzled store ----
    {
        const int qrow = t >> 1;                 // 0..63
        const int cbase = (t & 1) * 64;
        const float* qr = gq + ((size_t)(b * CE + e0 + qrow) * CH + h) * CD;
        #pragma unroll
        for (int g = 0; g < 8; ++g) {
            int colf = cbase + 8 * g;
            float4 x0 = *(const float4*)(qr + colf);
            float4 x1 = *(const float4*)(qr + colf + 4);
            x0.x *= SCALE_L2E; x0.y *= SCALE_L2E; x0.z *= SCALE_L2E; x0.w *= SCALE_L2E;
            x1.x *= SCALE_L2E; x1.y *= SCALE_L2E; x1.z *= SCALE_L2E; x1.w *= SCALE_L2E;
            uint4 hi, lo;
            split2h(x0.x, x0.y, hi.x, lo.x);
            split2h(x0.z, x0.w, hi.y, lo.y);
            split2h(x1.x, x1.y, hi.z, lo.z);
            split2h(x1.z, x1.w, hi.w, lo.w);
            uint32_t off = swz(qrow, (uint32_t)colf * 2);
            *(uint4*)(smem + OFF_QH + off) = hi;
            *(uint4*)(smem + OFF_QL + off) = lo;
        }
    }
    __syncthreads();

    // ---- persistent Q hi/lo fragments ----
    const uint32_t qrow = 16 * w + (lane & 7) + 8 * ((lane >> 3) & 1);
    const uint32_t qbc0 = 16 * (lane >> 4);
    uint32_t qh[8][4], ql[8][4];
    #pragma unroll
    for (int kk = 0; kk < 8; ++kk) {
        ldsm4(qh[kk], sb + OFF_QH + swz(qrow, qbc0 + kk * 32));
        ldsm4(ql[kk], sb + OFF_QL + swz(qrow, qbc0 + kk * 32));
    }

    const uint32_t rB  = (lane & 7) + 8 * (lane >> 4);
    const uint32_t bcB = 16 * ((lane >> 3) & 1);
    const uint32_t rV  = (lane & 7) + 8 * ((lane >> 3) & 1);
    const uint32_t bcV = 16 * (lane >> 4);

    const int row0 = 16 * w + (lane >> 2);       // 0..63
    const int lim0 = CP + e0 + row0;
    const int lim1 = lim0 + 8;
    float m0 = NEG_INF, m1 = NEG_INF, l0 = 0.0f, l1 = 0.0f;

    float o[16][4];
    #pragma unroll
    for (int j = 0; j < 16; ++j)
        #pragma unroll
        for (int c = 0; c < 4; ++c) o[j][c] = 0.0f;

    for (int kt = 0; kt < ntiles; ++kt) {
        const int s0 = kt * TK;
        const uint32_t stage = sb + OFF_ST + (kt & 1) * STAGE_STRIDE;

        __syncthreads();

        if (kt + 1 < ntiles) {
            const uint32_t tile_off = (((uint32_t)khb * CS + (s0 + TK)) << 8);
            const uint32_t dstb = sb + OFF_ST + ((kt + 1) & 1) * STAGE_STRIDE;
            #pragma unroll
            for (int u = 0; u < 16; ++u) {
                int idx = u * NTHREADS + t;
                int plane = idx >> 10;
                int off = (idx & 1023) * 16;
                cpa16(dstb + plane * PLANE_STRIDE + off,
                      g_scr + (size_t)plane * SCR_PLANE + tile_off + off);
            }
        }
        CPA_COMMIT();
        CPA_WAIT1();
        __syncthreads();

        // ---- phase 1: S = (Qh + Ql) Kh^T, double-buffered K fragments ----
        float s[8][4];
        #pragma unroll
        for (int nt = 0; nt < 8; ++nt)
            #pragma unroll
            for (int c = 0; c < 4; ++c) s[nt][c] = 0.0f;

        uint32_t kf[2][4];
        ldsm4(kf[0], stage + swz(rB, bcB));

        #pragma unroll
        for (int it = 0; it < 32; ++it) {
            const int kk = it >> 2, ng = it & 3;
            const int cur = it & 1, nxt = cur ^ 1;
            if (it + 1 < 32) {
                const int kk2 = (it + 1) >> 2, ng2 = (it + 1) & 3;
                ldsm4(kf[nxt], stage + swz(16 * ng2 + rB, bcB + kk2 * 32));
            }
            mma16816h(s[2 * ng],     qh[kk], kf[cur][0], kf[cur][1]);
            mma16816h(s[2 * ng + 1], qh[kk], kf[cur][2], kf[cur][3]);
            mma16816h(s[2 * ng],     ql[kk], kf[cur][0], kf[cur][1]);
            mma16816h(s[2 * ng + 1], ql[kk], kf[cur][2], kf[cur][3]);
        }

        // ---- mask (only last 2 tiles) ----
        if (s0 + TK - 1 > CP + e0) {
            const int j0 = s0 + 2 * (lane & 3);
            #pragma unroll
            for (int nt = 0; nt < 8; ++nt) {
                int jj = j0 + 8 * nt;
                if (jj     > lim0) s[nt][0] = NEG_INF;
                if (jj + 1 > lim0) s[nt][1] = NEG_INF;
                if (jj     > lim1) s[nt][2] = NEG_INF;
                if (jj + 1 > lim1) s[nt][3] = NEG_INF;
            }
        }

        // ---- online softmax (log2 domain) ----
        float mt0 = NEG_INF, mt1 = NEG_INF;
        #pragma unroll
        for (int nt = 0; nt < 8; ++nt) {
            mt0 = fmaxf(mt0, fmaxf(s[nt][0], s[nt][1]));
            mt1 = fmaxf(mt1, fmaxf(s[nt][2], s[nt][3]));
        }
        mt0 = fmaxf(mt0, __shfl_xor_sync(0xffffffffu, mt0, 1));
        mt0 = fmaxf(mt0, __shfl_xor_sync(0xffffffffu, mt0, 2));
        mt1 = fmaxf(mt1, __shfl_xor_sync(0xffffffffu, mt1, 1));
        mt1 = fmaxf(mt1, __shfl_xor_sync(0xffffffffu, mt1, 2));

        float mn0 = fmaxf(m0, mt0), mn1 = fmaxf(m1, mt1);
        float sc0 = ex2(m0 - mn0), sc1 = ex2(m1 - mn1);
        m0 = mn0; m1 = mn1;

        float ps0 = 0.0f, ps1 = 0.0f;
        #pragma unroll
        for (int nt = 0; nt < 8; ++nt) {
            s[nt][0] = ex2(s[nt][0] - mn0);
            s[nt][1] = ex2(s[nt][1] - mn0);
            s[nt][2] = ex2(s[nt][2] - mn1);
            s[nt][3] = ex2(s[nt][3] - mn1);
            ps0 += s[nt][0] + s[nt][1];
            ps1 += s[nt][2] + s[nt][3];
        }
        ps0 += __shfl_xor_sync(0xffffffffu, ps0, 1);
        ps0 += __shfl_xor_sync(0xffffffffu, ps0, 2);
        ps1 += __shfl_xor_sync(0xffffffffu, ps1, 1);
        ps1 += __shfl_xor_sync(0xffffffffu, ps1, 2);
        l0 = l0 * sc0 + ps0;
        l1 = l1 * sc1 + ps1;

        #pragma unroll
        for (int j = 0; j < 16; ++j) {
            o[j][0] *= sc0; o[j][1] *= sc0;
            o[j][2] *= sc1; o[j][3] *= sc1;
        }

        // ---- phase 2: O += (Ph + Pl) Vh, double-buffered V fragments ----
        uint32_t vf[2][4];
        ldsm4t(vf[0], stage + PLANE_STRIDE + swz(rV, bcV));

        uint32_t ah[4], al[4];
        split2h(s[0][0], s[0][1], ah[0], al[0]);
        split2h(s[0][2], s[0][3], ah[1], al[1]);
        split2h(s[1][0], s[1][1], ah[2], al[2]);
        split2h(s[1][2], s[1][3], ah[3], al[3]);

        #pragma unroll
        for (int it = 0; it < 32; ++it) {
            const int kk = it >> 3, ng = it & 7;
            const int cur = it & 1, nxt = cur ^ 1;
            if (it + 1 < 32) {
                const int kk2 = (it + 1) >> 3, ng2 = (it + 1) & 7;
                ldsm4t(vf[nxt], stage + PLANE_STRIDE + swz(16 * kk2 + rV, bcV + 32 * ng2));
            }
            mma16816h(o[2 * ng],     ah, vf[cur][0], vf[cur][1]);
            mma16816h(o[2 * ng + 1], ah, vf[cur][2], vf[cur][3]);
            mma16816h(o[2 * ng],     al, vf[cur][0], vf[cur][1]);
            mma16816h(o[2 * ng + 1], al, vf[cur][2], vf[cur][3]);
            if (ng == 7 && kk < 3) {
                split2h(s[2 * kk + 2][0], s[2 * kk + 2][1], ah[0], al[0]);
                split2h(s[2 * kk + 2][2], s[2 * kk + 2][3], ah[1], al[1]);
                split2h(s[2 * kk + 3][0], s[2 * kk + 3][1], ah[2], al[2]);
                split2h(s[2 * kk + 3][2], s[2 * kk + 3][3], ah[3], al[3]);
            }
        }
    }

    // ---- epilogue ----
    const float inv0 = 1.0f / l0, inv1 = 1.0f / l1;
    float* orow0 = out + (size_t)(b * CE + e0 + row0) * (CH * CD) + h * CD;
    float* orow1 = orow0 + (size_t)8 * (CH * CD);
    const int dc = 2 * (lane & 3);
    #pragma unroll
    for (int j = 0; j < 16; ++j) {
        float2 f0 = make_float2(o[j][0] * inv0, o[j][1] * inv0);
        float2 f1 = make_float2(o[j][2] * inv1, o[j][3] * inv1);
        *(float2*)(orow0 + 8 * j + dc) = f0;
        *(float2*)(orow1 + 8 * j + dc) = f1;
    }
}

extern "C" void kernel_launch(void* const* d_in, const int* in_sizes, int n_in,
                              void* d_out, int out_size) {
    (void)in_sizes; (void)n_in; (void)out_size;
    const float* q  = (const float*)d_in[0];
    const float* k  = (const float*)d_in[1];
    const float* v  = (const float*)d_in[2];
    const float* kc = (const float*)d_in[3];
    const float* vc = (const float*)d_in[4];
    float* out = (float*)d_out;

    prep_kv<<<(CB * CHK * CS * 16) / 256, 256>>>(k, v, kc, vc);

    cudaFuncSetAttribute(radix_extend_hmma,
                         cudaFuncAttributeMaxDynamicSharedMemorySize, SMEM_BYTES);
    dim3 grid(CE / TQ, CH, CB);   // (8, 32, 4) = 1024 CTAs
    radix_extend_hmma<<<grid, NTHREADS, SMEM_BYTES>>>(q, out);
}

// round 10
// speedup vs baseline: 6.6306x; 1.1687x over previous
#include <cuda_runtime.h>
#include <cstdint>
#include <cstddef>

#define CB 4
#define CE 512
#define CP 1536
#define CH 32
#define CHK 8
#define CD 128
#define CS 2048
#define TQ 64
#define TK 64
#define NTHREADS 128
// SCALE * log2(e): scores computed directly in log2 domain
#define SCALE_L2E 0.12751741814489405f
#define NEG_INF -1e30f

// scratch: fp16 K and V planes in swizzled layout, 256B per row
#define SCR_PLANE (16u * 1024 * 1024)
__device__ __align__(256) unsigned char g_scr[2ull * SCR_PLANE];  // K, V

// smem: Q hi/lo planes (16KB each) + 2-stage K/V buffers (32KB each)
#define OFF_QH 0
#define OFF_QL 16384
#define OFF_ST 32768
#define STAGE_STRIDE 32768
#define PLANE_STRIDE 16384
#define SMEM_BYTES 98304

__device__ __forceinline__ uint32_t swz(uint32_t row, uint32_t byteCol) {
    return (row << 8) + (byteCol ^ ((row & 7) << 4));
}

__device__ __forceinline__ uint32_t smem_u32(const void* p) {
    uint32_t a;
    asm("{ .reg .u64 t; cvta.to.shared.u64 t, %1; cvt.u32.u64 %0, t; }"
        : "=r"(a) : "l"(p));
    return a;
}

__device__ __forceinline__ float ex2(float x) {
    float y;
    asm("ex2.approx.ftz.f32 %0, %1;" : "=f"(y) : "f"(x));
    return y;
}

// pack two floats to f16x2 (rn)
__device__ __forceinline__ uint32_t packh(float x0, float x1) {
    uint32_t r;
    asm("cvt.rn.f16x2.f32 %0, %1, %2;" : "=r"(r) : "f"(x1), "f"(x0));
    return r;
}

// split pair of floats into f16x2 hi (rn) + f16x2 lo (residual)
__device__ __forceinline__ void split2h(float x0, float x1,
                                        uint32_t& hp, uint32_t& lp) {
    asm("cvt.rn.f16x2.f32 %0, %1, %2;" : "=r"(hp) : "f"(x1), "f"(x0));
    float h0, h1;
    asm("{ .reg .b16 a, b;\n\t"
        "mov.b32 {a, b}, %2;\n\t"
        "cvt.f32.f16 %0, a;\n\t"
        "cvt.f32.f16 %1, b; }"
        : "=f"(h0), "=f"(h1) : "r"(hp));
    float l0 = x0 - h0, l1 = x1 - h1;
    asm("cvt.rn.f16x2.f32 %0, %1, %2;" : "=r"(lp) : "f"(l1), "f"(l0));
}

__device__ __forceinline__ void ldsm4(uint32_t r[4], uint32_t addr) {
    asm volatile("ldmatrix.sync.aligned.m8n8.x4.shared.b16 {%0,%1,%2,%3}, [%4];"
                 : "=r"(r[0]), "=r"(r[1]), "=r"(r[2]), "=r"(r[3]) : "r"(addr));
}
__device__ __forceinline__ void ldsm4t(uint32_t r[4], uint32_t addr) {
    asm volatile("ldmatrix.sync.aligned.m8n8.x4.trans.shared.b16 {%0,%1,%2,%3}, [%4];"
                 : "=r"(r[0]), "=r"(r[1]), "=r"(r[2]), "=r"(r[3]) : "r"(addr));
}

__device__ __forceinline__ void mma16816h(float c[4], const uint32_t a[4],
                                          uint32_t b0, uint32_t b1) {
    asm volatile(
        "mma.sync.aligned.m16n8k16.row.col.f32.f16.f16.f32 "
        "{%0,%1,%2,%3}, {%4,%5,%6,%7}, {%8,%9}, {%0,%1,%2,%3};"
        : "+f"(c[0]), "+f"(c[1]), "+f"(c[2]), "+f"(c[3])
        : "r"(a[0]), "r"(a[1]), "r"(a[2]), "r"(a[3]), "r"(b0), "r"(b1));
}

__device__ __forceinline__ void cpa16(uint32_t dst, const void* src) {
    asm volatile("cp.async.cg.shared.global [%0], [%1], 16;"
                 :: "r"(dst), "l"(src) : "memory");
}
#define CPA_COMMIT() asm volatile("cp.async.commit_group;" ::: "memory")
#define CPA_WAIT1()  asm volatile("cp.async.wait_group 1;" ::: "memory")

// ---------------- prep kernel: fp32 K/V -> swizzled fp16 planes ----------------
__global__ __launch_bounds__(256)
void prep_kv(const float* __restrict__ gk,  const float* __restrict__ gv,
             const float* __restrict__ gkc, const float* __restrict__ gvc) {
    const int task = blockIdx.x * 256 + threadIdx.x;
    const int g   = task & 15;
    const int s   = (task >> 4) & (CS - 1);
    const int khb = task >> 15;
    const int kh  = khb & 7, b = khb >> 3;

    const float *kr, *vr;
    if (s < CP) {
        size_t o = ((size_t)(b * CP + s) * CHK + kh) * CD;
        kr = gkc + o; vr = gvc + o;
    } else {
        size_t o = ((size_t)(b * CE + (s - CP)) * CHK + kh) * CD;
        kr = gk + o; vr = gv + o;
    }
    const int col = g * 8;
    const uint32_t dst = (((uint32_t)khb * CS + s) << 8) + ((g * 16) ^ ((s & 7) << 4));

    float4 x0 = *(const float4*)(kr + col);
    float4 x1 = *(const float4*)(kr + col + 4);
    uint4 p;
    p.x = packh(x0.x, x0.y); p.y = packh(x0.z, x0.w);
    p.z = packh(x1.x, x1.y); p.w = packh(x1.z, x1.w);
    *(uint4*)(g_scr + 0ull * SCR_PLANE + dst) = p;

    x0 = *(const float4*)(vr + col);
    x1 = *(const float4*)(vr + col + 4);
    p.x = packh(x0.x, x0.y); p.y = packh(x0.z, x0.w);
    p.z = packh(x1.x, x1.y); p.w = packh(x1.z, x1.w);
    *(uint4*)(g_scr + 1ull * SCR_PLANE + dst) = p;
}

// ---------------- main attention kernel (2 CTAs/SM) ----------------
__global__ __launch_bounds__(NTHREADS, 2)
void radix_extend_hmma(const float* __restrict__ gq, float* __restrict__ out) {
    extern __shared__ char smem[];
    const uint32_t sb = smem_u32(smem);
    const int t = threadIdx.x, w = t >> 5, lane = t & 31;
    const int e0 = blockIdx.x * TQ, h = blockIdx.y, b = blockIdx.z;
    const int khb = b * CHK + (h >> 2);
    const int ntiles = (CP + e0 + TQ) / TK;

    // prefetch tile 0 (K+V planes, 32KB) while we convert Q
    {
        const uint32_t tile_off = (((uint32_t)khb * CS) << 8);
        #pragma unroll
        for (int u = 0; u < 16; ++u) {
            int idx = u * NTHREADS + t;          // 0..2047
            int plane = idx >> 10;
            int off = (idx & 1023) * 16;
            cpa16(sb + OFF_ST + plane * PLANE_STRIDE + off,
                  g_scr + (size_t)plane * SCR_PLANE + tile_off + off);
        }
    }
    CPA_COMMIT();

    // ---- load Q tile: fold scale*log2e, split fp16 hi/lo, swizzled store ----
    {
        const int qrow = t >> 1;                 // 0..63
        const int cbase = (t & 1) * 64;
        const float* qr = gq + ((size_t)(b * CE + e0 + qrow) * CH + h) * CD;
        #pragma unroll
        for (int g = 0; g < 8; ++g) {
            int colf = cbase + 8 * g;
            float4 x0 = *(const float4*)(qr + colf);
            float4 x1 = *(const float4*)(qr + colf + 4);
            x0.x *= SCALE_L2E; x0.y *= SCALE_L2E; x0.z *= SCALE_L2E; x0.w *= SCALE_L2E;
            x1.x *= SCALE_L2E; x1.y *= SCALE_L2E; x1.z *= SCALE_L2E; x1.w *= SCALE_L2E;
            uint4 hi, lo;
            split2h(x0.x, x0.y, hi.x, lo.x);
            split2h(x0.z, x0.w, hi.y, lo.y);
            split2h(x1.x, x1.y, hi.z, lo.z);
            split2h(x1.z, x1.w, hi.w, lo.w);
            uint32_t off = swz(qrow, (uint32_t)colf * 2);
            *(uint4*)(smem + OFF_QH + off) = hi;
            *(uint4*)(smem + OFF_QL + off) = lo;
        }
    }
    __syncthreads();

    // ---- persistent Q hi/lo fragments ----
    const uint32_t qrow = 16 * w + (lane & 7) + 8 * ((lane >> 3) & 1);
    const uint32_t qbc0 = 16 * (lane >> 4);
    uint32_t qh[8][4], ql[8][4];
    #pragma unroll
    for (int kk = 0; kk < 8; ++kk) {
        ldsm4(qh[kk], sb + OFF_QH + swz(qrow, qbc0 + kk * 32));
        ldsm4(ql[kk], sb + OFF_QL + swz(qrow, qbc0 + kk * 32));
    }

    const uint32_t rB  = (lane & 7) + 8 * (lane >> 4);
    const uint32_t bcB = 16 * ((lane >> 3) & 1);
    const uint32_t rV  = (lane & 7) + 8 * ((lane >> 3) & 1);
    const uint32_t bcV = 16 * (lane >> 4);

    const int row0 = 16 * w + (lane >> 2);       // 0..63
    const int lim0 = CP + e0 + row0;
    const int lim1 = lim0 + 8;
    float m0 = NEG_INF, m1 = NEG_INF, l0 = 0.0f, l1 = 0.0f;

    float o[16][4];
    #pragma unroll
    for (int j = 0; j < 16; ++j)
        #pragma unroll
        for (int c = 0; c < 4; ++c) o[j][c] = 0.0f;

    for (int kt = 0; kt < ntiles; ++kt) {
        const int s0 = kt * TK;
        const uint32_t stage = sb + OFF_ST + (kt & 1) * STAGE_STRIDE;

        __syncthreads();

        if (kt + 1 < ntiles) {
            const uint32_t tile_off = (((uint32_t)khb * CS + (s0 + TK)) << 8);
            const uint32_t dstb = sb + OFF_ST + ((kt + 1) & 1) * STAGE_STRIDE;
            #pragma unroll
            for (int u = 0; u < 16; ++u) {
                int idx = u * NTHREADS + t;
                int plane = idx >> 10;
                int off = (idx & 1023) * 16;
                cpa16(dstb + plane * PLANE_STRIDE + off,
                      g_scr + (size_t)plane * SCR_PLANE + tile_off + off);
            }
        }
        CPA_COMMIT();
        CPA_WAIT1();
        __syncthreads();

        // ---- phase 1: S = (Qh + Ql) Kh^T, double-buffered K fragments ----
        float s[8][4];
        #pragma unroll
        for (int nt = 0; nt < 8; ++nt)
            #pragma unroll
            for (int c = 0; c < 4; ++c) s[nt][c] = 0.0f;

        uint32_t kf[2][4];
        ldsm4(kf[0], stage + swz(rB, bcB));

        #pragma unroll
        for (int it = 0; it < 32; ++it) {
            const int kk = it >> 2, ng = it & 3;
            const int cur = it & 1, nxt = cur ^ 1;
            if (it + 1 < 32) {
                const int kk2 = (it + 1) >> 2, ng2 = (it + 1) & 3;
                ldsm4(kf[nxt], stage + swz(16 * ng2 + rB, bcB + kk2 * 32));
            }
            mma16816h(s[2 * ng],     qh[kk], kf[cur][0], kf[cur][1]);
            mma16816h(s[2 * ng + 1], qh[kk], kf[cur][2], kf[cur][3]);
            mma16816h(s[2 * ng],     ql[kk], kf[cur][0], kf[cur][1]);
            mma16816h(s[2 * ng + 1], ql[kk], kf[cur][2], kf[cur][3]);
        }

        // ---- mask (only last 2 tiles) ----
        if (s0 + TK - 1 > CP + e0) {
            const int j0 = s0 + 2 * (lane & 3);
            #pragma unroll
            for (int nt = 0; nt < 8; ++nt) {
                int jj = j0 + 8 * nt;
                if (jj     > lim0) s[nt][0] = NEG_INF;
                if (jj + 1 > lim0) s[nt][1] = NEG_INF;
                if (jj     > lim1) s[nt][2] = NEG_INF;
                if (jj + 1 > lim1) s[nt][3] = NEG_INF;
            }
        }

        // ---- online softmax (log2 domain) ----
        float mt0 = NEG_INF, mt1 = NEG_INF;
        #pragma unroll
        for (int nt = 0; nt < 8; ++nt) {
            mt0 = fmaxf(mt0, fmaxf(s[nt][0], s[nt][1]));
            mt1 = fmaxf(mt1, fmaxf(s[nt][2], s[nt][3]));
        }
        mt0 = fmaxf(mt0, __shfl_xor_sync(0xffffffffu, mt0, 1));
        mt0 = fmaxf(mt0, __shfl_xor_sync(0xffffffffu, mt0, 2));
        mt1 = fmaxf(mt1, __shfl_xor_sync(0xffffffffu, mt1, 1));
        mt1 = fmaxf(mt1, __shfl_xor_sync(0xffffffffu, mt1, 2));

        float mn0 = fmaxf(m0, mt0), mn1 = fmaxf(m1, mt1);
        float sc0 = ex2(m0 - mn0), sc1 = ex2(m1 - mn1);
        m0 = mn0; m1 = mn1;

        float ps0 = 0.0f, ps1 = 0.0f;
        #pragma unroll
        for (int nt = 0; nt < 8; ++nt) {
            s[nt][0] = ex2(s[nt][0] - mn0);
            s[nt][1] = ex2(s[nt][1] - mn0);
            s[nt][2] = ex2(s[nt][2] - mn1);
            s[nt][3] = ex2(s[nt][3] - mn1);
            ps0 += s[nt][0] + s[nt][1];
            ps1 += s[nt][2] + s[nt][3];
        }
        ps0 += __shfl_xor_sync(0xffffffffu, ps0, 1);
        ps0 += __shfl_xor_sync(0xffffffffu, ps0, 2);
        ps1 += __shfl_xor_sync(0xffffffffu, ps1, 1);
        ps1 += __shfl_xor_sync(0xffffffffu, ps1, 2);
        l0 = l0 * sc0 + ps0;
        l1 = l1 * sc1 + ps1;

        #pragma unroll
        for (int j = 0; j < 16; ++j) {
            o[j][0] *= sc0; o[j][1] *= sc0;
            o[j][2] *= sc1; o[j][3] *= sc1;
        }

        // ---- phase 2: O += Ph Vh (P quantized fp16), double-buffered V frags ----
        uint32_t vf[2][4];
        ldsm4t(vf[0], stage + PLANE_STRIDE + swz(rV, bcV));

        uint32_t ah[4];
        ah[0] = packh(s[0][0], s[0][1]);
        ah[1] = packh(s[0][2], s[0][3]);
        ah[2] = packh(s[1][0], s[1][1]);
        ah[3] = packh(s[1][2], s[1][3]);

        #pragma unroll
        for (int it = 0; it < 32; ++it) {
            const int kk = it >> 3, ng = it & 7;
            const int cur = it & 1, nxt = cur ^ 1;
            if (it + 1 < 32) {
                const int kk2 = (it + 1) >> 3, ng2 = (it + 1) & 7;
                ldsm4t(vf[nxt], stage + PLANE_STRIDE + swz(16 * kk2 + rV, bcV + 32 * ng2));
            }
            mma16816h(o[2 * ng],     ah, vf[cur][0], vf[cur][1]);
            mma16816h(o[2 * ng + 1], ah, vf[cur][2], vf[cur][3]);
            if (ng == 7 && kk < 3) {
                ah[0] = packh(s[2 * kk + 2][0], s[2 * kk + 2][1]);
                ah[1] = packh(s[2 * kk + 2][2], s[2 * kk + 2][3]);
                ah[2] = packh(s[2 * kk + 3][0], s[2 * kk + 3][1]);
                ah[3] = packh(s[2 * kk + 3][2], s[2 * kk + 3][3]);
            }
        }
    }

    // ---- epilogue ----
    const float inv0 = 1.0f / l0, inv1 = 1.0f / l1;
    float* orow0 = out + (size_t)(b * CE + e0 + row0) * (CH * CD) + h * CD;
    float* orow1 = orow0 + (size_t)8 * (CH * CD);
    const int dc = 2 * (lane & 3);
    #pragma unroll
    for (int j = 0; j < 16; ++j) {
        float2 f0 = make_float2(o[j][0] * inv0, o[j][1] * inv0);
        float2 f1 = make_float2(o[j][2] * inv1, o[j][3] * inv1);
        *(float2*)(orow0 + 8 * j + dc) = f0;
        *(float2*)(orow1 + 8 * j + dc) = f1;
    }
}

extern "C" void kernel_launch(void* const* d_in, const int* in_sizes, int n_in,
                              void* d_out, int out_size) {
    (void)in_sizes; (void)n_in; (void)out_size;
    const float* q  = (const float*)d_in[0];
    const float* k  = (const float*)d_in[1];
    const float* v  = (const float*)d_in[2];
    const float* kc = (const float*)d_in[3];
    const float* vc = (const float*)d_in[4];
    float* out = (float*)d_out;

    prep_kv<<<(CB * CHK * CS * 16) / 256, 256>>>(k, v, kc, vc);

    cudaFuncSetAttribute(radix_extend_hmma,
                         cudaFuncAttributeMaxDynamicSharedMemorySize, SMEM_BYTES);
    dim3 grid(CE / TQ, CH, CB);   // (8, 32, 4) = 1024 CTAs
    radix_extend_hmma<<<grid, NTHREADS, SMEM_BYTES>>>(q, out);
}

// round 11
// speedup vs baseline: 8.0602x; 1.2156x over previous
#include <cuda_runtime.h>
#include <cstdint>
#include <cstddef>

#define CB 4
#define CE 512
#define CP 1536
#define CH 32
#define CHK 8
#define CD 128
#define CS 2048
#define TQ 64
#define TK 64
#define NTHREADS 128
// SCALE * log2(e): scores computed directly in log2 domain
#define SCALE_L2E 0.12751741814489405f
#define NEG_INF -1e30f

// scratch: fp16 K and V planes in swizzled layout, 256B per row
#define SCR_PLANE (16u * 1024 * 1024)
__device__ __align__(256) unsigned char g_scr[2ull * SCR_PLANE];  // K, V

// smem: Q plane (16KB) + 3-stage K/V buffers (32KB each)
#define OFF_QH 0
#define OFF_ST 16384
#define STAGE_STRIDE 32768
#define PLANE_STRIDE 16384
#define SMEM_BYTES 114688

__device__ __forceinline__ uint32_t swz(uint32_t row, uint32_t byteCol) {
    return (row << 8) + (byteCol ^ ((row & 7) << 4));
}

__device__ __forceinline__ uint32_t smem_u32(const void* p) {
    uint32_t a;
    asm("{ .reg .u64 t; cvta.to.shared.u64 t, %1; cvt.u32.u64 %0, t; }"
        : "=r"(a) : "l"(p));
    return a;
}

__device__ __forceinline__ float ex2(float x) {
    float y;
    asm("ex2.approx.ftz.f32 %0, %1;" : "=f"(y) : "f"(x));
    return y;
}

// pack two floats to f16x2 (rn)
__device__ __forceinline__ uint32_t packh(float x0, float x1) {
    uint32_t r;
    asm("cvt.rn.f16x2.f32 %0, %1, %2;" : "=r"(r) : "f"(x1), "f"(x0));
    return r;
}

__device__ __forceinline__ void ldsm4(uint32_t r[4], uint32_t addr) {
    asm volatile("ldmatrix.sync.aligned.m8n8.x4.shared.b16 {%0,%1,%2,%3}, [%4];"
                 : "=r"(r[0]), "=r"(r[1]), "=r"(r[2]), "=r"(r[3]) : "r"(addr));
}
__device__ __forceinline__ void ldsm4t(uint32_t r[4], uint32_t addr) {
    asm volatile("ldmatrix.sync.aligned.m8n8.x4.trans.shared.b16 {%0,%1,%2,%3}, [%4];"
                 : "=r"(r[0]), "=r"(r[1]), "=r"(r[2]), "=r"(r[3]) : "r"(addr));
}

__device__ __forceinline__ void mma16816h(float c[4], const uint32_t a[4],
                                          uint32_t b0, uint32_t b1) {
    asm volatile(
        "mma.sync.aligned.m16n8k16.row.col.f32.f16.f16.f32 "
        "{%0,%1,%2,%3}, {%4,%5,%6,%7}, {%8,%9}, {%0,%1,%2,%3};"
        : "+f"(c[0]), "+f"(c[1]), "+f"(c[2]), "+f"(c[3])
        : "r"(a[0]), "r"(a[1]), "r"(a[2]), "r"(a[3]), "r"(b0), "r"(b1));
}

__device__ __forceinline__ void cpa16(uint32_t dst, const void* src) {
    asm volatile("cp.async.cg.shared.global [%0], [%1], 16;"
                 :: "r"(dst), "l"(src) : "memory");
}
#define CPA_COMMIT() asm volatile("cp.async.commit_group;" ::: "memory")
#define CPA_WAIT2()  asm volatile("cp.async.wait_group 2;" ::: "memory")

// ---------------- prep kernel: fp32 K/V -> swizzled fp16 planes ----------------
__global__ __launch_bounds__(256)
void prep_kv(const float* __restrict__ gk,  const float* __restrict__ gv,
             const float* __restrict__ gkc, const float* __restrict__ gvc) {
    const int task = blockIdx.x * 256 + threadIdx.x;
    const int g   = task & 15;
    const int s   = (task >> 4) & (CS - 1);
    const int khb = task >> 15;
    const int kh  = khb & 7, b = khb >> 3;

    const float *kr, *vr;
    if (s < CP) {
        size_t o = ((size_t)(b * CP + s) * CHK + kh) * CD;
        kr = gkc + o; vr = gvc + o;
    } else {
        size_t o = ((size_t)(b * CE + (s - CP)) * CHK + kh) * CD;
        kr = gk + o; vr = gv + o;
    }
    const int col = g * 8;
    const uint32_t dst = (((uint32_t)khb * CS + s) << 8) + ((g * 16) ^ ((s & 7) << 4));

    float4 x0 = *(const float4*)(kr + col);
    float4 x1 = *(const float4*)(kr + col + 4);
    uint4 p;
    p.x = packh(x0.x, x0.y); p.y = packh(x0.z, x0.w);
    p.z = packh(x1.x, x1.y); p.w = packh(x1.z, x1.w);
    *(uint4*)(g_scr + 0ull * SCR_PLANE + dst) = p;

    x0 = *(const float4*)(vr + col);
    x1 = *(const float4*)(vr + col + 4);
    p.x = packh(x0.x, x0.y); p.y = packh(x0.z, x0.w);
    p.z = packh(x1.x, x1.y); p.w = packh(x1.z, x1.w);
    *(uint4*)(g_scr + 1ull * SCR_PLANE + dst) = p;
}

// ---------------- main attention kernel (2 CTAs/SM, 3-stage pipeline) ----------------
__global__ __launch_bounds__(NTHREADS, 2)
void radix_extend_hmma(const float* __restrict__ gq, float* __restrict__ out) {
    extern __shared__ char smem[];
    const uint32_t sb = smem_u32(smem);
    const int t = threadIdx.x, w = t >> 5, lane = t & 31;
    const int e0 = blockIdx.x * TQ, h = blockIdx.y, b = blockIdx.z;
    const int khb = b * CHK + (h >> 2);
    const int ntiles = (CP + e0 + TQ) / TK;

    // prefetch tiles 0 and 1 (one commit group each)
    #pragma unroll
    for (int pre = 0; pre < 2; ++pre) {
        const uint32_t tile_off = (((uint32_t)khb * CS + pre * TK) << 8);
        const uint32_t dstb = sb + OFF_ST + pre * STAGE_STRIDE;
        #pragma unroll
        for (int u = 0; u < 16; ++u) {
            int idx = u * NTHREADS + t;          // 0..2047
            int plane = idx >> 10;
            int off = (idx & 1023) * 16;
            cpa16(dstb + plane * PLANE_STRIDE + off,
                  g_scr + (size_t)plane * SCR_PLANE + tile_off + off);
        }
        CPA_COMMIT();
    }

    // ---- load Q tile: fold scale*log2e, quantize fp16, swizzled store ----
    {
        const int qrow = t >> 1;                 // 0..63
        const int cbase = (t & 1) * 64;
        const float* qr = gq + ((size_t)(b * CE + e0 + qrow) * CH + h) * CD;
        #pragma unroll
        for (int g = 0; g < 8; ++g) {
            int colf = cbase + 8 * g;
            float4 x0 = *(const float4*)(qr + colf);
            float4 x1 = *(const float4*)(qr + colf + 4);
            uint4 hi;
            hi.x = packh(x0.x * SCALE_L2E, x0.y * SCALE_L2E);
            hi.y = packh(x0.z * SCALE_L2E, x0.w * SCALE_L2E);
            hi.z = packh(x1.x * SCALE_L2E, x1.y * SCALE_L2E);
            hi.w = packh(x1.z * SCALE_L2E, x1.w * SCALE_L2E);
            *(uint4*)(smem + OFF_QH + swz(qrow, (uint32_t)colf * 2)) = hi;
        }
    }
    __syncthreads();

    // ---- persistent Q fragments ----
    const uint32_t qrow = 16 * w + (lane & 7) + 8 * ((lane >> 3) & 1);
    const uint32_t qbc0 = 16 * (lane >> 4);
    uint32_t qh[8][4];
    #pragma unroll
    for (int kk = 0; kk < 8; ++kk)
        ldsm4(qh[kk], sb + OFF_QH + swz(qrow, qbc0 + kk * 32));

    const uint32_t rB  = (lane & 7) + 8 * (lane >> 4);
    const uint32_t bcB = 16 * ((lane >> 3) & 1);
    const uint32_t rV  = (lane & 7) + 8 * ((lane >> 3) & 1);
    const uint32_t bcV = 16 * (lane >> 4);

    const int row0 = 16 * w + (lane >> 2);       // 0..63
    const int lim0 = CP + e0 + row0;
    const int lim1 = lim0 + 8;
    float m0 = NEG_INF, m1 = NEG_INF, l0 = 0.0f, l1 = 0.0f;

    float o[16][4];
    #pragma unroll
    for (int j = 0; j < 16; ++j)
        #pragma unroll
        for (int c = 0; c < 4; ++c) o[j][c] = 0.0f;

    int stg = 0;   // kt % 3
    for (int kt = 0; kt < ntiles; ++kt) {
        const int s0 = kt * TK;
        const uint32_t stage = sb + OFF_ST + stg * STAGE_STRIDE;

        __syncthreads();   // all warps done reading the buffer we're about to overwrite

        // prefetch tile kt+2 into stage (kt+2)%3; always commit (uniform group count)
        if (kt + 2 < ntiles) {
            int stg2 = stg + 2 >= 3 ? stg - 1 : stg + 2;
            const uint32_t tile_off = (((uint32_t)khb * CS + (s0 + 2 * TK)) << 8);
            const uint32_t dstb = sb + OFF_ST + stg2 * STAGE_STRIDE;
            #pragma unroll
            for (int u = 0; u < 16; ++u) {
                int idx = u * NTHREADS + t;
                int plane = idx >> 10;
                int off = (idx & 1023) * 16;
                cpa16(dstb + plane * PLANE_STRIDE + off,
                      g_scr + (size_t)plane * SCR_PLANE + tile_off + off);
            }
        }
        CPA_COMMIT();
        CPA_WAIT2();       // tile kt landed (≤2 groups still in flight)
        __syncthreads();

        // ---- phase 1: S = Qh Kh^T, double-buffered K fragments ----
        float s[8][4];
        #pragma unroll
        for (int nt = 0; nt < 8; ++nt)
            #pragma unroll
            for (int c = 0; c < 4; ++c) s[nt][c] = 0.0f;

        uint32_t kf[2][4];
        ldsm4(kf[0], stage + swz(rB, bcB));

        #pragma unroll
        for (int it = 0; it < 32; ++it) {
            const int kk = it >> 2, ng = it & 3;
            const int cur = it & 1, nxt = cur ^ 1;
            if (it + 1 < 32) {
                const int kk2 = (it + 1) >> 2, ng2 = (it + 1) & 3;
                ldsm4(kf[nxt], stage + swz(16 * ng2 + rB, bcB + kk2 * 32));
            }
            mma16816h(s[2 * ng],     qh[kk], kf[cur][0], kf[cur][1]);
            mma16816h(s[2 * ng + 1], qh[kk], kf[cur][2], kf[cur][3]);
        }

        // ---- mask (only last 2 tiles) ----
        if (s0 + TK - 1 > CP + e0) {
            const int j0 = s0 + 2 * (lane & 3);
            #pragma unroll
            for (int nt = 0; nt < 8; ++nt) {
                int jj = j0 + 8 * nt;
                if (jj     > lim0) s[nt][0] = NEG_INF;
                if (jj + 1 > lim0) s[nt][1] = NEG_INF;
                if (jj     > lim1) s[nt][2] = NEG_INF;
                if (jj + 1 > lim1) s[nt][3] = NEG_INF;
            }
        }

        // ---- online softmax (log2 domain) ----
        float mt0 = NEG_INF, mt1 = NEG_INF;
        #pragma unroll
        for (int nt = 0; nt < 8; ++nt) {
            mt0 = fmaxf(mt0, fmaxf(s[nt][0], s[nt][1]));
            mt1 = fmaxf(mt1, fmaxf(s[nt][2], s[nt][3]));
        }
        mt0 = fmaxf(mt0, __shfl_xor_sync(0xffffffffu, mt0, 1));
        mt0 = fmaxf(mt0, __shfl_xor_sync(0xffffffffu, mt0, 2));
        mt1 = fmaxf(mt1, __shfl_xor_sync(0xffffffffu, mt1, 1));
        mt1 = fmaxf(mt1, __shfl_xor_sync(0xffffffffu, mt1, 2));

        float mn0 = fmaxf(m0, mt0), mn1 = fmaxf(m1, mt1);
        float sc0 = ex2(m0 - mn0), sc1 = ex2(m1 - mn1);
        m0 = mn0; m1 = mn1;

        float ps0 = 0.0f, ps1 = 0.0f;
        #pragma unroll
        for (int nt = 0; nt < 8; ++nt) {
            s[nt][0] = ex2(s[nt][0] - mn0);
            s[nt][1] = ex2(s[nt][1] - mn0);
            s[nt][2] = ex2(s[nt][2] - mn1);
            s[nt][3] = ex2(s[nt][3] - mn1);
            ps0 += s[nt][0] + s[nt][1];
            ps1 += s[nt][2] + s[nt][3];
        }
        ps0 += __shfl_xor_sync(0xffffffffu, ps0, 1);
        ps0 += __shfl_xor_sync(0xffffffffu, ps0, 2);
        ps1 += __shfl_xor_sync(0xffffffffu, ps1, 1);
        ps1 += __shfl_xor_sync(0xffffffffu, ps1, 2);
        l0 = l0 * sc0 + ps0;
        l1 = l1 * sc1 + ps1;

        #pragma unroll
        for (int j = 0; j < 16; ++j) {
            o[j][0] *= sc0; o[j][1] *= sc0;
            o[j][2] *= sc1; o[j][3] *= sc1;
        }

        // ---- phase 2: O += Ph Vh, double-buffered V fragments ----
        uint32_t vf[2][4];
        ldsm4t(vf[0], stage + PLANE_STRIDE + swz(rV, bcV));

        uint32_t ah[4];
        ah[0] = packh(s[0][0], s[0][1]);
        ah[1] = packh(s[0][2], s[0][3]);
        ah[2] = packh(s[1][0], s[1][1]);
        ah[3] = packh(s[1][2], s[1][3]);

        #pragma unroll
        for (int it = 0; it < 32; ++it) {
            const int kk = it >> 3, ng = it & 7;
            const int cur = it & 1, nxt = cur ^ 1;
            if (it + 1 < 32) {
                const int kk2 = (it + 1) >> 3, ng2 = (it + 1) & 7;
                ldsm4t(vf[nxt], stage + PLANE_STRIDE + swz(16 * kk2 + rV, bcV + 32 * ng2));
            }
            mma16816h(o[2 * ng],     ah, vf[cur][0], vf[cur][1]);
            mma16816h(o[2 * ng + 1], ah, vf[cur][2], vf[cur][3]);
            if (ng == 7 && kk < 3) {
                ah[0] = packh(s[2 * kk + 2][0], s[2 * kk + 2][1]);
                ah[1] = packh(s[2 * kk + 2][2], s[2 * kk + 2][3]);
                ah[2] = packh(s[2 * kk + 3][0], s[2 * kk + 3][1]);
                ah[3] = packh(s[2 * kk + 3][2], s[2 * kk + 3][3]);
            }
        }

        stg = (stg + 1 == 3) ? 0 : stg + 1;
    }

    // ---- epilogue ----
    const float inv0 = 1.0f / l0, inv1 = 1.0f / l1;
    float* orow0 = out + (size_t)(b * CE + e0 + row0) * (CH * CD) + h * CD;
    float* orow1 = orow0 + (size_t)8 * (CH * CD);
    const int dc = 2 * (lane & 3);
    #pragma unroll
    for (int j = 0; j < 16; ++j) {
        float2 f0 = make_float2(o[j][0] * inv0, o[j][1] * inv0);
        float2 f1 = make_float2(o[j][2] * inv1, o[j][3] * inv1);
        *(float2*)(orow0 + 8 * j + dc) = f0;
        *(float2*)(orow1 + 8 * j + dc) = f1;
    }
}

extern "C" void kernel_launch(void* const* d_in, const int* in_sizes, int n_in,
                              void* d_out, int out_size) {
    (void)in_sizes; (void)n_in; (void)out_size;
    const float* q  = (const float*)d_in[0];
    const float* k  = (const float*)d_in[1];
    const float* v  = (const float*)d_in[2];
    const float* kc = (const float*)d_in[3];
    const float* vc = (const float*)d_in[4];
    float* out = (float*)d_out;

    prep_kv<<<(CB * CHK * CS * 16) / 256, 256>>>(k, v, kc, vc);

    cudaFuncSetAttribute(radix_extend_hmma,
                         cudaFuncAttributeMaxDynamicSharedMemorySize, SMEM_BYTES);
    dim3 grid(CE / TQ, CH, CB);   // (8, 32, 4) = 1024 CTAs
    radix_extend_hmma<<<grid, NTHREADS, SMEM_BYTES>>>(q, out);
}